// round 6
// baseline (speedup 1.0000x reference)
#include <cuda_runtime.h>
#include <math.h>

// Problem constants
#define NN    50000
#define EE    800000
#define DIN   64
#define HIDD  128
#define DOUTC 64
#define BB    2

// ---------------- scratch (static device globals; no allocation) ----------------
__device__ float g_h [BB * NN * 128];   // projected features for current layer
__device__ float g_el[BB * NN * 2];     // per-node attention left  (max 2 heads)
__device__ float g_er[BB * NN * 2];     // per-node attention right
__device__ float g_y1[BB * NN * 128];   // layer1 output
__device__ float g_y2[BB * NN * 128];   // layer2 output
__device__ float g_w [BB * EE * 2];     // per-edge softmax numerators, CSR order
__device__ int   g_rowptr[NN + 1];      // CSR by dst
__device__ int   g_cursor[NN];          // degree / scatter cursor
__device__ int   g_csrc[EE];            // src per CSR slot
__device__ int   g_cdst[EE];            // dst per CSR slot (quasi-sorted)

// ---------------- packed fp32x2 helpers ----------------
__device__ __forceinline__ void fma2(unsigned long long& d,
                                     unsigned long long a,
                                     unsigned long long b) {
    asm("fma.rn.f32x2 %0, %1, %2, %0;" : "+l"(d) : "l"(a), "l"(b));
}
__device__ __forceinline__ float2 up2(unsigned long long v) {
    float2 r;
    asm("mov.b64 {%0, %1}, %2;" : "=f"(r.x), "=f"(r.y) : "l"(v));
    return r;
}

// ---------------- CSR build ----------------
__global__ void zero_deg_kernel() {
    int i = blockIdx.x * blockDim.x + threadIdx.x;
    if (i < NN) g_cursor[i] = 0;
}

__global__ void hist_kernel(const int* __restrict__ dst) {
    int e = blockIdx.x * blockDim.x + threadIdx.x;
    if (e < EE) atomicAdd(&g_cursor[dst[e]], 1);
}

__global__ void scan_kernel() {
    __shared__ int ss[1024];
    const int t  = threadIdx.x;
    const int CH = (NN + 1023) / 1024;
    const int b  = t * CH;
    const int e  = min(b + CH, NN);
    int s = 0;
    for (int i = b; i < e; i++) s += g_cursor[i];
    ss[t] = s;
    __syncthreads();
    for (int off = 1; off < 1024; off <<= 1) {
        int v = (t >= off) ? ss[t - off] : 0;
        __syncthreads();
        ss[t] += v;
        __syncthreads();
    }
    int run = (t == 0) ? 0 : ss[t - 1];
    for (int i = b; i < e; i++) {
        int d = g_cursor[i];
        g_rowptr[i] = run;
        g_cursor[i] = run;
        run += d;
    }
    if (t == 1023) g_rowptr[NN] = ss[1023];
}

__global__ void scatter_kernel(const int* __restrict__ src, const int* __restrict__ dst) {
    int e = blockIdx.x * blockDim.x + threadIdx.x;
    if (e < EE) {
        int d = dst[e];
        int p = atomicAdd(&g_cursor[d], 1);
        g_csrc[p] = src[e];
        g_cdst[p] = d;
    }
}

// ---------------- tiled GEMM (f32x2) + attention coefficients ----------------
template <int K, int HD, int H>
__global__ __launch_bounds__(256) void gemm_att_kernel(
    const float* __restrict__ xbase, size_t xstride,
    const float* __restrict__ W,
    const float* __restrict__ al, const float* __restrict__ ar,
    float* __restrict__ hbase, float* __restrict__ elbase, float* __restrict__ erbase)
{
    constexpr int TM  = 64;
    constexpr int KC  = 16;
    constexpr int CG  = HD / 4;
    constexpr int RT  = TM / (256 / CG);
    constexpr int NP  = RT / 2;
    constexpr int D   = HD / H;
    constexpr int LPHW = (CG / H) < 32 ? (CG / H) : 32;
    constexpr int WITER = (KC * HD / 4 + 255) / 256;

    __shared__ __align__(16) float xs [KC][TM + 4];
    __shared__ __align__(16) float ws2[KC][2 * HD];

    const float* x    = xbase  + (size_t)blockIdx.y * xstride;
    float*       hout = hbase  + (size_t)blockIdx.y * NN * HD;
    float*       el   = elbase + (size_t)blockIdx.y * NN * H;
    float*       er   = erbase + (size_t)blockIdx.y * NN * H;

    const int tid  = threadIdx.x;
    const int lane = tid & 31;
    const int cg   = tid % CG;
    const int rg   = tid / CG;
    const int c0   = cg * 4;
    const int rb   = rg * RT;
    const int row0 = blockIdx.x * TM;

    unsigned long long acc[NP][4];
    #pragma unroll
    for (int p = 0; p < NP; p++)
        #pragma unroll
        for (int c = 0; c < 4; c++) acc[p][c] = 0ull;

    const int lr = tid >> 2;
    const int lj = tid & 3;
    const int lrow = min(row0 + lr, NN - 1);
    const float4* xrow = reinterpret_cast<const float4*>(x + (size_t)lrow * K);

    for (int kc = 0; kc < K; kc += KC) {
        float4 xv = xrow[(kc >> 2) + lj];
        xs[lj * 4 + 0][lr] = xv.x;
        xs[lj * 4 + 1][lr] = xv.y;
        xs[lj * 4 + 2][lr] = xv.z;
        xs[lj * 4 + 3][lr] = xv.w;
        #pragma unroll
        for (int it = 0; it < WITER; it++) {
            int fi = tid + it * 256;
            if (fi < KC * HD / 4) {
                int k  = fi / (HD / 4);
                int cq = fi % (HD / 4);
                float4 wv = *reinterpret_cast<const float4*>(W + (size_t)(kc + k) * HD + cq * 4);
                *reinterpret_cast<float4*>(&ws2[k][cq * 8])     = make_float4(wv.x, wv.x, wv.y, wv.y);
                *reinterpret_cast<float4*>(&ws2[k][cq * 8 + 4]) = make_float4(wv.z, wv.z, wv.w, wv.w);
            }
        }
        __syncthreads();

        #pragma unroll
        for (int k = 0; k < KC; k++) {
            ulonglong2 wa = *reinterpret_cast<const ulonglong2*>(&ws2[k][2 * c0]);
            ulonglong2 wb = *reinterpret_cast<const ulonglong2*>(&ws2[k][2 * c0 + 4]);
            ulonglong2 xa = *reinterpret_cast<const ulonglong2*>(&xs[k][rb]);
            fma2(acc[0][0], xa.x, wa.x);
            fma2(acc[0][1], xa.x, wa.y);
            fma2(acc[0][2], xa.x, wb.x);
            fma2(acc[0][3], xa.x, wb.y);
            fma2(acc[1][0], xa.y, wa.x);
            fma2(acc[1][1], xa.y, wa.y);
            fma2(acc[1][2], xa.y, wb.x);
            fma2(acc[1][3], xa.y, wb.y);
            if constexpr (NP == 4) {
                ulonglong2 xb = *reinterpret_cast<const ulonglong2*>(&xs[k][rb + 4]);
                fma2(acc[2][0], xb.x, wa.x);
                fma2(acc[2][1], xb.x, wa.y);
                fma2(acc[2][2], xb.x, wb.x);
                fma2(acc[2][3], xb.x, wb.y);
                fma2(acc[3][0], xb.y, wa.x);
                fma2(acc[3][1], xb.y, wa.y);
                fma2(acc[3][2], xb.y, wb.x);
                fma2(acc[3][3], xb.y, wb.y);
            }
        }
        __syncthreads();
    }

    float vals[RT][4];
    #pragma unroll
    for (int p = 0; p < NP; p++)
        #pragma unroll
        for (int c = 0; c < 4; c++) {
            float2 f = up2(acc[p][c]);
            vals[p * 2 + 0][c] = f.x;
            vals[p * 2 + 1][c] = f.y;
        }

    #pragma unroll
    for (int i = 0; i < RT; i++) {
        int row = row0 + rb + i;
        if (row < NN)
            *reinterpret_cast<float4*>(hout + (size_t)row * HD + c0) =
                make_float4(vals[i][0], vals[i][1], vals[i][2], vals[i][3]);
    }

    float al4[4], ar4[4];
    #pragma unroll
    for (int c = 0; c < 4; c++) { al4[c] = al[c0 + c]; ar4[c] = ar[c0 + c]; }
    const int hh = c0 / D;

    #pragma unroll
    for (int i = 0; i < RT; i++) {
        float pel = 0.f, per_ = 0.f;
        #pragma unroll
        for (int c = 0; c < 4; c++) {
            pel  = fmaf(vals[i][c], al4[c], pel);
            per_ = fmaf(vals[i][c], ar4[c], per_);
        }
        #pragma unroll
        for (int off = LPHW >> 1; off > 0; off >>= 1) {
            pel  += __shfl_xor_sync(0xffffffffu, pel,  off);
            per_ += __shfl_xor_sync(0xffffffffu, per_, off);
        }
        int row = row0 + rb + i;
        if ((lane & (LPHW - 1)) == 0 && row < NN) {
            el[row * H + hh] = pel;
            er[row * H + hh] = per_;
        }
    }
}

// ---------------- per-edge softmax numerators (CSR order, both batches) ------
template <int H>
__global__ __launch_bounds__(256) void weight_kernel(
    const float* __restrict__ elbase, const float* __restrict__ erbase)
{
    int p = blockIdx.x * blockDim.x + threadIdx.x;
    if (p >= EE) return;
    const int s = g_csrc[p];
    const int d = g_cdst[p];
    const float* el0 = elbase;
    const float* el1 = elbase + NN * H;
    const float* er0 = erbase;
    const float* er1 = erbase + NN * H;
    float* w0 = g_w;
    float* w1 = g_w + (size_t)EE * H;
    #pragma unroll
    for (int h = 0; h < H; h++) {
        float v0 = el0[s * H + h] + er0[d * H + h];
        float v1 = el1[s * H + h] + er1[d * H + h];
        v0 = (v0 > 0.f) ? v0 : 0.2f * v0;
        v1 = (v1 > 0.f) ? v1 : 0.2f * v1;
        w0[p * H + h] = __expf(v0);
        w1[p * H + h] = __expf(v1);
    }
}

// ---------------- aggregation: feature-split warps, both batches -------------
// Each warp owns a 64-float chunk of one node's output (VW=2). HD=128 layers
// get 2 warps per node -> 2x concurrent latency chains; 256B coalesced gathers.
template <int HD, int H, bool RELU>
__global__ __launch_bounds__(256, 4) void aggregate4_kernel(
    const float* __restrict__ hbase, const float* __restrict__ bias,
    float* __restrict__ outbase, size_t outstride)
{
    constexpr int SPL = HD / 64;    // warps per node (1 or 2)
    constexpr int D   = HD / H;

    const float* h0 = hbase;
    const float* h1 = hbase + (size_t)NN * HD;
    const float* w0 = g_w;
    const float* w1 = g_w + (size_t)EE * H;
    float*       o0 = outbase;
    float*       o1 = outbase + outstride;

    const int gw   = (blockIdx.x * blockDim.x + threadIdx.x) >> 5;
    const int lane = threadIdx.x & 31;
    const int node = gw / SPL;
    const int part = gw % SPL;
    if (node >= NN) return;

    const int s0 = g_rowptr[node];
    const int s1 = g_rowptr[node + 1];
    const int c0 = part * 64 + lane * 2;
    const int hl = c0 / D;

    float2 acc0 = make_float2(0.f, 0.f);
    float2 acc1 = make_float2(0.f, 0.f);
    float sum0 = 0.f, sum1 = 0.f;

    int p = s0;
    for (; p + 4 <= s1; p += 4) {
        const int iA = g_csrc[p];
        const int iB = g_csrc[p + 1];
        const int iC = g_csrc[p + 2];
        const int iD = g_csrc[p + 3];
        const float wa0 = w0[(p + 0) * H + hl];
        const float wb0 = w0[(p + 1) * H + hl];
        const float wc0 = w0[(p + 2) * H + hl];
        const float wd0 = w0[(p + 3) * H + hl];
        const float wa1 = w1[(p + 0) * H + hl];
        const float wb1 = w1[(p + 1) * H + hl];
        const float wc1 = w1[(p + 2) * H + hl];
        const float wd1 = w1[(p + 3) * H + hl];

        float2 A0 = *reinterpret_cast<const float2*>(h0 + (size_t)iA * HD + c0);
        float2 B0 = *reinterpret_cast<const float2*>(h0 + (size_t)iB * HD + c0);
        float2 C0 = *reinterpret_cast<const float2*>(h0 + (size_t)iC * HD + c0);
        float2 D0 = *reinterpret_cast<const float2*>(h0 + (size_t)iD * HD + c0);
        float2 A1 = *reinterpret_cast<const float2*>(h1 + (size_t)iA * HD + c0);
        float2 B1 = *reinterpret_cast<const float2*>(h1 + (size_t)iB * HD + c0);
        float2 C1 = *reinterpret_cast<const float2*>(h1 + (size_t)iC * HD + c0);
        float2 D1 = *reinterpret_cast<const float2*>(h1 + (size_t)iD * HD + c0);

        sum0 += (wa0 + wb0) + (wc0 + wd0);
        sum1 += (wa1 + wb1) + (wc1 + wd1);

        acc0.x = fmaf(wa0, A0.x, acc0.x); acc0.x = fmaf(wb0, B0.x, acc0.x);
        acc0.x = fmaf(wc0, C0.x, acc0.x); acc0.x = fmaf(wd0, D0.x, acc0.x);
        acc0.y = fmaf(wa0, A0.y, acc0.y); acc0.y = fmaf(wb0, B0.y, acc0.y);
        acc0.y = fmaf(wc0, C0.y, acc0.y); acc0.y = fmaf(wd0, D0.y, acc0.y);
        acc1.x = fmaf(wa1, A1.x, acc1.x); acc1.x = fmaf(wb1, B1.x, acc1.x);
        acc1.x = fmaf(wc1, C1.x, acc1.x); acc1.x = fmaf(wd1, D1.x, acc1.x);
        acc1.y = fmaf(wa1, A1.y, acc1.y); acc1.y = fmaf(wb1, B1.y, acc1.y);
        acc1.y = fmaf(wc1, C1.y, acc1.y); acc1.y = fmaf(wd1, D1.y, acc1.y);
    }
    for (; p < s1; p++) {
        const int iA = g_csrc[p];
        const float wa0 = w0[p * H + hl];
        const float wa1 = w1[p * H + hl];
        sum0 += wa0;
        sum1 += wa1;
        float2 A0 = *reinterpret_cast<const float2*>(h0 + (size_t)iA * HD + c0);
        float2 A1 = *reinterpret_cast<const float2*>(h1 + (size_t)iA * HD + c0);
        acc0.x = fmaf(wa0, A0.x, acc0.x);
        acc0.y = fmaf(wa0, A0.y, acc0.y);
        acc1.x = fmaf(wa1, A1.x, acc1.x);
        acc1.y = fmaf(wa1, A1.y, acc1.y);
    }

    const float bx = bias[c0];
    const float by = bias[c0 + 1];

    float2 out0, out1;
    if (s1 > s0) {
        const float i0 = 1.f / sum0;
        const float i1 = 1.f / sum1;
        out0 = make_float2(fmaf(acc0.x, i0, bx), fmaf(acc0.y, i0, by));
        out1 = make_float2(fmaf(acc1.x, i1, bx), fmaf(acc1.y, i1, by));
    } else {
        out0 = make_float2(bx, by);
        out1 = make_float2(bx, by);
    }
    if (RELU) {
        out0.x = fmaxf(out0.x, 0.f); out0.y = fmaxf(out0.y, 0.f);
        out1.x = fmaxf(out1.x, 0.f); out1.y = fmaxf(out1.y, 0.f);
    }

    *reinterpret_cast<float2*>(o0 + (size_t)node * HD + c0) = out0;
    *reinterpret_cast<float2*>(o1 + (size_t)node * HD + c0) = out1;
}

// ---------------- launcher ----------------
extern "C" void kernel_launch(void* const* d_in, const int* in_sizes, int n_in,
                              void* d_out, int out_size)
{
    const float* input = (const float*)d_in[0];
    const int*   src   = (const int*)  d_in[1];
    const int*   dst   = (const int*)  d_in[2];
    const float* W1    = (const float*)d_in[3];
    const float* al1   = (const float*)d_in[4];
    const float* ar1   = (const float*)d_in[5];
    const float* b1    = (const float*)d_in[6];
    const float* W2    = (const float*)d_in[7];
    const float* al2   = (const float*)d_in[8];
    const float* ar2   = (const float*)d_in[9];
    const float* b2    = (const float*)d_in[10];
    const float* W3    = (const float*)d_in[11];
    const float* al3   = (const float*)d_in[12];
    const float* ar3   = (const float*)d_in[13];
    const float* b3    = (const float*)d_in[14];
    float* out = (float*)d_out;

    void *ph, *pel, *per, *py1, *py2;
    cudaGetSymbolAddress(&ph,  g_h);
    cudaGetSymbolAddress(&pel, g_el);
    cudaGetSymbolAddress(&per, g_er);
    cudaGetSymbolAddress(&py1, g_y1);
    cudaGetSymbolAddress(&py2, g_y2);
    float* hbuf = (float*)ph;
    float* elb  = (float*)pel;
    float* erb  = (float*)per;
    float* y1   = (float*)py1;
    float* y2   = (float*)py2;

    // CSR build (edges identical across batches/layers -> build once per launch)
    zero_deg_kernel<<<(NN + 255) / 256, 256>>>();
    hist_kernel<<<(EE + 255) / 256, 256>>>(dst);
    scan_kernel<<<1, 1024>>>();
    scatter_kernel<<<(EE + 255) / 256, 256>>>(src, dst);

    dim3 ggrid((NN + 63) / 64, BB);
    const int wgrid  = (EE + 255) / 256;
    const int agrid2 = (NN * 2 * 32 + 255) / 256;   // HD=128: 2 warps/node
    const int agrid1 = (NN * 1 * 32 + 255) / 256;   // HD=64 : 1 warp/node

    // Layer 1: GATConv(64 -> 2 heads x 64)
    gemm_att_kernel<64, 128, 2><<<ggrid, 256>>>(input, (size_t)NN * DIN, W1, al1, ar1, hbuf, elb, erb);
    weight_kernel<2><<<wgrid, 256>>>(elb, erb);
    aggregate4_kernel<128, 2, false><<<agrid2, 256>>>(hbuf, b1, y1, (size_t)NN * 128);

    // Layer 2: GATConv(128 -> 128, 1 head), ReLU
    gemm_att_kernel<128, 128, 1><<<ggrid, 256>>>(y1, (size_t)NN * 128, W2, al2, ar2, hbuf, elb, erb);
    weight_kernel<1><<<wgrid, 256>>>(elb, erb);
    aggregate4_kernel<128, 1, true><<<agrid2, 256>>>(hbuf, b2, y2, (size_t)NN * 128);

    // Layer 3: GATConv(128 -> 64, 1 head)
    gemm_att_kernel<128, 64, 1><<<ggrid, 256>>>(y2, (size_t)NN * 128, W3, al3, ar3, hbuf, elb, erb);
    weight_kernel<1><<<wgrid, 256>>>(elb, erb);
    aggregate4_kernel<64, 1, false><<<agrid1, 256>>>(hbuf, b3, out, (size_t)NN * DOUTC);
}

// round 7
// speedup vs baseline: 1.1051x; 1.1051x over previous
#include <cuda_runtime.h>
#include <cuda_fp16.h>
#include <math.h>

// Problem constants
#define NN    50000
#define EE    800000
#define DIN   64
#define HIDD  128
#define DOUTC 64
#define BB    2

// ---------------- scratch (static device globals; no allocation) ----------------
__device__ __half g_h [BB * NN * 128];  // projected features (fp16 gather table)
__device__ float  g_el[BB * NN * 2];    // per-node attention left  (max 2 heads)
__device__ float  g_er[BB * NN * 2];    // per-node attention right
__device__ float  g_y1[BB * NN * 128];  // layer1 output
__device__ float  g_y2[BB * NN * 128];  // layer2 output
__device__ int    g_rowptr[NN + 1];     // CSR by dst
__device__ int    g_cursor[NN];         // degree / scatter cursor
__device__ int    g_csrc[EE];           // src per CSR slot

// ---------------- packed fp32x2 helpers ----------------
__device__ __forceinline__ void fma2(unsigned long long& d,
                                     unsigned long long a,
                                     unsigned long long b) {
    asm("fma.rn.f32x2 %0, %1, %2, %0;" : "+l"(d) : "l"(a), "l"(b));
}
__device__ __forceinline__ float2 up2(unsigned long long v) {
    float2 r;
    asm("mov.b64 {%0, %1}, %2;" : "=f"(r.x), "=f"(r.y) : "l"(v));
    return r;
}

// ---------------- fp16 gather helpers ----------------
__device__ __forceinline__ float4 ldh4(const __half* p) {
    uint2 u = *reinterpret_cast<const uint2*>(p);
    float2 fa = __half22float2(*reinterpret_cast<const __half2*>(&u.x));
    float2 fb = __half22float2(*reinterpret_cast<const __half2*>(&u.y));
    return make_float4(fa.x, fa.y, fb.x, fb.y);
}
__device__ __forceinline__ float2 ldh2(const __half* p) {
    unsigned u = *reinterpret_cast<const unsigned*>(p);
    return __half22float2(*reinterpret_cast<const __half2*>(&u));
}

// ---------------- CSR build ----------------
__global__ void zero_deg_kernel() {
    int i = blockIdx.x * blockDim.x + threadIdx.x;
    if (i < NN) g_cursor[i] = 0;
}

__global__ void hist_kernel(const int* __restrict__ dst) {
    int e = blockIdx.x * blockDim.x + threadIdx.x;
    if (e < EE) atomicAdd(&g_cursor[dst[e]], 1);
}

__global__ void scan_kernel() {
    __shared__ int ss[1024];
    const int t  = threadIdx.x;
    const int CH = (NN + 1023) / 1024;
    const int b  = t * CH;
    const int e  = min(b + CH, NN);
    int s = 0;
    for (int i = b; i < e; i++) s += g_cursor[i];
    ss[t] = s;
    __syncthreads();
    for (int off = 1; off < 1024; off <<= 1) {
        int v = (t >= off) ? ss[t - off] : 0;
        __syncthreads();
        ss[t] += v;
        __syncthreads();
    }
    int run = (t == 0) ? 0 : ss[t - 1];
    for (int i = b; i < e; i++) {
        int d = g_cursor[i];
        g_rowptr[i] = run;
        g_cursor[i] = run;
        run += d;
    }
    if (t == 1023) g_rowptr[NN] = ss[1023];
}

__global__ void scatter_kernel(const int* __restrict__ src, const int* __restrict__ dst) {
    int e = blockIdx.x * blockDim.x + threadIdx.x;
    if (e < EE) {
        int p = atomicAdd(&g_cursor[dst[e]], 1);
        g_csrc[p] = src[e];
    }
}

// ---------------- tiled GEMM (f32x2) + attention coefficients ----------------
// Stores h as fp16 (consumed only by the gather-aggregate). el/er from fp32 accs.
template <int K, int HD, int H>
__global__ __launch_bounds__(256) void gemm_att_kernel(
    const float* __restrict__ xbase, size_t xstride,
    const float* __restrict__ W,
    const float* __restrict__ al, const float* __restrict__ ar,
    __half* __restrict__ hbase, float* __restrict__ elbase, float* __restrict__ erbase)
{
    constexpr int TM  = 64;
    constexpr int KC  = 16;
    constexpr int CG  = HD / 4;
    constexpr int RT  = TM / (256 / CG);
    constexpr int NP  = RT / 2;
    constexpr int D   = HD / H;
    constexpr int LPHW = (CG / H) < 32 ? (CG / H) : 32;
    constexpr int WITER = (KC * HD / 4 + 255) / 256;

    __shared__ __align__(16) float xs [KC][TM + 4];
    __shared__ __align__(16) float ws2[KC][2 * HD];

    const float* x    = xbase  + (size_t)blockIdx.y * xstride;
    __half*      hout = hbase  + (size_t)blockIdx.y * NN * HD;
    float*       el   = elbase + (size_t)blockIdx.y * NN * H;
    float*       er   = erbase + (size_t)blockIdx.y * NN * H;

    const int tid  = threadIdx.x;
    const int lane = tid & 31;
    const int cg   = tid % CG;
    const int rg   = tid / CG;
    const int c0   = cg * 4;
    const int rb   = rg * RT;
    const int row0 = blockIdx.x * TM;

    unsigned long long acc[NP][4];
    #pragma unroll
    for (int p = 0; p < NP; p++)
        #pragma unroll
        for (int c = 0; c < 4; c++) acc[p][c] = 0ull;

    const int lr = tid >> 2;
    const int lj = tid & 3;
    const int lrow = min(row0 + lr, NN - 1);
    const float4* xrow = reinterpret_cast<const float4*>(x + (size_t)lrow * K);

    for (int kc = 0; kc < K; kc += KC) {
        float4 xv = xrow[(kc >> 2) + lj];
        xs[lj * 4 + 0][lr] = xv.x;
        xs[lj * 4 + 1][lr] = xv.y;
        xs[lj * 4 + 2][lr] = xv.z;
        xs[lj * 4 + 3][lr] = xv.w;
        #pragma unroll
        for (int it = 0; it < WITER; it++) {
            int fi = tid + it * 256;
            if (fi < KC * HD / 4) {
                int k  = fi / (HD / 4);
                int cq = fi % (HD / 4);
                float4 wv = *reinterpret_cast<const float4*>(W + (size_t)(kc + k) * HD + cq * 4);
                *reinterpret_cast<float4*>(&ws2[k][cq * 8])     = make_float4(wv.x, wv.x, wv.y, wv.y);
                *reinterpret_cast<float4*>(&ws2[k][cq * 8 + 4]) = make_float4(wv.z, wv.z, wv.w, wv.w);
            }
        }
        __syncthreads();

        #pragma unroll
        for (int k = 0; k < KC; k++) {
            ulonglong2 wa = *reinterpret_cast<const ulonglong2*>(&ws2[k][2 * c0]);
            ulonglong2 wb = *reinterpret_cast<const ulonglong2*>(&ws2[k][2 * c0 + 4]);
            ulonglong2 xa = *reinterpret_cast<const ulonglong2*>(&xs[k][rb]);
            fma2(acc[0][0], xa.x, wa.x);
            fma2(acc[0][1], xa.x, wa.y);
            fma2(acc[0][2], xa.x, wb.x);
            fma2(acc[0][3], xa.x, wb.y);
            fma2(acc[1][0], xa.y, wa.x);
            fma2(acc[1][1], xa.y, wa.y);
            fma2(acc[1][2], xa.y, wb.x);
            fma2(acc[1][3], xa.y, wb.y);
            if constexpr (NP == 4) {
                ulonglong2 xb = *reinterpret_cast<const ulonglong2*>(&xs[k][rb + 4]);
                fma2(acc[2][0], xb.x, wa.x);
                fma2(acc[2][1], xb.x, wa.y);
                fma2(acc[2][2], xb.x, wb.x);
                fma2(acc[2][3], xb.x, wb.y);
                fma2(acc[3][0], xb.y, wa.x);
                fma2(acc[3][1], xb.y, wa.y);
                fma2(acc[3][2], xb.y, wb.x);
                fma2(acc[3][3], xb.y, wb.y);
            }
        }
        __syncthreads();
    }

    float vals[RT][4];
    #pragma unroll
    for (int p = 0; p < NP; p++)
        #pragma unroll
        for (int c = 0; c < 4; c++) {
            float2 f = up2(acc[p][c]);
            vals[p * 2 + 0][c] = f.x;
            vals[p * 2 + 1][c] = f.y;
        }

    // ---- store h (fp16) ----
    #pragma unroll
    for (int i = 0; i < RT; i++) {
        int row = row0 + rb + i;
        if (row < NN) {
            union { __half2 h2[2]; uint2 u; } cv;
            cv.h2[0] = __floats2half2_rn(vals[i][0], vals[i][1]);
            cv.h2[1] = __floats2half2_rn(vals[i][2], vals[i][3]);
            *reinterpret_cast<uint2*>(hout + (size_t)row * HD + c0) = cv.u;
        }
    }

    float al4[4], ar4[4];
    #pragma unroll
    for (int c = 0; c < 4; c++) { al4[c] = al[c0 + c]; ar4[c] = ar[c0 + c]; }
    const int hh = c0 / D;

    #pragma unroll
    for (int i = 0; i < RT; i++) {
        float pel = 0.f, per_ = 0.f;
        #pragma unroll
        for (int c = 0; c < 4; c++) {
            pel  = fmaf(vals[i][c], al4[c], pel);
            per_ = fmaf(vals[i][c], ar4[c], per_);
        }
        #pragma unroll
        for (int off = LPHW >> 1; off > 0; off >>= 1) {
            pel  += __shfl_xor_sync(0xffffffffu, pel,  off);
            per_ += __shfl_xor_sync(0xffffffffu, per_, off);
        }
        int row = row0 + rb + i;
        if ((lane & (LPHW - 1)) == 0 && row < NN) {
            el[row * H + hh] = pel;
            er[row * H + hh] = per_;
        }
    }
}

// ---------------- fused edge-softmax + aggregation, BOTH batches per warp ----
// R3 structure (proven fastest): in-loop exp, 2-edge unroll, node-per-warp.
// h gathers are fp16 -> half the L2 gather bytes.
template <int HD, int H, bool RELU>
__global__ __launch_bounds__(256) void aggregate_kernel(
    const __half* __restrict__ hbase, const float* __restrict__ elbase,
    const float* __restrict__ erbase, const float* __restrict__ bias,
    float* __restrict__ outbase, size_t outstride)
{
    constexpr int VW = HD / 32;
    constexpr int D  = HD / H;

    const __half* h0  = hbase;
    const __half* h1  = hbase  + (size_t)NN * HD;
    const float*  el0 = elbase;
    const float*  el1 = elbase + (size_t)NN * H;
    const float*  er0 = erbase;
    const float*  er1 = erbase + (size_t)NN * H;
    float*        o0  = outbase;
    float*        o1  = outbase + outstride;

    const int gw   = (blockIdx.x * blockDim.x + threadIdx.x) >> 5;
    const int lane = threadIdx.x & 31;
    if (gw >= NN) return;

    const int s0 = g_rowptr[gw];
    const int s1 = g_rowptr[gw + 1];
    const int c0 = lane * VW;
    const int hl = c0 / D;

    const float erA = er0[gw * H + hl];
    const float erB = er1[gw * H + hl];

    float acc0[VW], acc1[VW];
    #pragma unroll
    for (int j = 0; j < VW; j++) { acc0[j] = 0.f; acc1[j] = 0.f; }
    float sum0 = 0.f, sum1 = 0.f;

    int e = s0;
    for (; e + 1 < s1; e += 2) {
        const int sA = g_csrc[e];
        const int sB = g_csrc[e + 1];
        const float ea0 = el0[sA * H + hl];
        const float ea1 = el1[sA * H + hl];
        const float eb0 = el0[sB * H + hl];
        const float eb1 = el1[sB * H + hl];
        const __half* pa0 = h0 + (size_t)sA * HD + c0;
        const __half* pa1 = h1 + (size_t)sA * HD + c0;
        const __half* pb0 = h0 + (size_t)sB * HD + c0;
        const __half* pb1 = h1 + (size_t)sB * HD + c0;

        float va0 = ea0 + erA; va0 = (va0 > 0.f) ? va0 : 0.2f * va0;
        float va1 = ea1 + erB; va1 = (va1 > 0.f) ? va1 : 0.2f * va1;
        float vb0 = eb0 + erA; vb0 = (vb0 > 0.f) ? vb0 : 0.2f * vb0;
        float vb1 = eb1 + erB; vb1 = (vb1 > 0.f) ? vb1 : 0.2f * vb1;
        const float wa0 = __expf(va0);
        const float wa1 = __expf(va1);
        const float wb0 = __expf(vb0);
        const float wb1 = __expf(vb1);
        sum0 += wa0 + wb0;
        sum1 += wa1 + wb1;

        if constexpr (VW == 4) {
            float4 A0 = ldh4(pa0);
            float4 A1 = ldh4(pa1);
            float4 B0 = ldh4(pb0);
            float4 B1 = ldh4(pb1);
            acc0[0] = fmaf(wa0, A0.x, acc0[0]); acc0[0] = fmaf(wb0, B0.x, acc0[0]);
            acc0[1] = fmaf(wa0, A0.y, acc0[1]); acc0[1] = fmaf(wb0, B0.y, acc0[1]);
            acc0[2] = fmaf(wa0, A0.z, acc0[2]); acc0[2] = fmaf(wb0, B0.z, acc0[2]);
            acc0[3] = fmaf(wa0, A0.w, acc0[3]); acc0[3] = fmaf(wb0, B0.w, acc0[3]);
            acc1[0] = fmaf(wa1, A1.x, acc1[0]); acc1[0] = fmaf(wb1, B1.x, acc1[0]);
            acc1[1] = fmaf(wa1, A1.y, acc1[1]); acc1[1] = fmaf(wb1, B1.y, acc1[1]);
            acc1[2] = fmaf(wa1, A1.z, acc1[2]); acc1[2] = fmaf(wb1, B1.z, acc1[2]);
            acc1[3] = fmaf(wa1, A1.w, acc1[3]); acc1[3] = fmaf(wb1, B1.w, acc1[3]);
        } else {
            float2 A0 = ldh2(pa0);
            float2 A1 = ldh2(pa1);
            float2 B0 = ldh2(pb0);
            float2 B1 = ldh2(pb1);
            acc0[0] = fmaf(wa0, A0.x, acc0[0]); acc0[0] = fmaf(wb0, B0.x, acc0[0]);
            acc0[1] = fmaf(wa0, A0.y, acc0[1]); acc0[1] = fmaf(wb0, B0.y, acc0[1]);
            acc1[0] = fmaf(wa1, A1.x, acc1[0]); acc1[0] = fmaf(wb1, B1.x, acc1[0]);
            acc1[1] = fmaf(wa1, A1.y, acc1[1]); acc1[1] = fmaf(wb1, B1.y, acc1[1]);
        }
    }
    if (e < s1) {
        const int sA = g_csrc[e];
        const float ea0 = el0[sA * H + hl];
        const float ea1 = el1[sA * H + hl];
        float va0 = ea0 + erA; va0 = (va0 > 0.f) ? va0 : 0.2f * va0;
        float va1 = ea1 + erB; va1 = (va1 > 0.f) ? va1 : 0.2f * va1;
        const float wa0 = __expf(va0);
        const float wa1 = __expf(va1);
        sum0 += wa0;
        sum1 += wa1;
        const __half* pa0 = h0 + (size_t)sA * HD + c0;
        const __half* pa1 = h1 + (size_t)sA * HD + c0;
        if constexpr (VW == 4) {
            float4 A0 = ldh4(pa0);
            float4 A1 = ldh4(pa1);
            acc0[0] = fmaf(wa0, A0.x, acc0[0]);
            acc0[1] = fmaf(wa0, A0.y, acc0[1]);
            acc0[2] = fmaf(wa0, A0.z, acc0[2]);
            acc0[3] = fmaf(wa0, A0.w, acc0[3]);
            acc1[0] = fmaf(wa1, A1.x, acc1[0]);
            acc1[1] = fmaf(wa1, A1.y, acc1[1]);
            acc1[2] = fmaf(wa1, A1.z, acc1[2]);
            acc1[3] = fmaf(wa1, A1.w, acc1[3]);
        } else {
            float2 A0 = ldh2(pa0);
            float2 A1 = ldh2(pa1);
            acc0[0] = fmaf(wa0, A0.x, acc0[0]);
            acc0[1] = fmaf(wa0, A0.y, acc0[1]);
            acc1[0] = fmaf(wa1, A1.x, acc1[0]);
            acc1[1] = fmaf(wa1, A1.y, acc1[1]);
        }
    }

    float bv[VW];
    #pragma unroll
    for (int j = 0; j < VW; j++) bv[j] = bias[c0 + j];

    float out0[VW], out1[VW];
    if (s1 > s0) {
        const float i0 = 1.f / sum0;
        const float i1 = 1.f / sum1;
        #pragma unroll
        for (int j = 0; j < VW; j++) {
            out0[j] = fmaf(acc0[j], i0, bv[j]);
            out1[j] = fmaf(acc1[j], i1, bv[j]);
        }
    } else {
        #pragma unroll
        for (int j = 0; j < VW; j++) { out0[j] = bv[j]; out1[j] = bv[j]; }
    }
    if (RELU) {
        #pragma unroll
        for (int j = 0; j < VW; j++) {
            out0[j] = fmaxf(out0[j], 0.f);
            out1[j] = fmaxf(out1[j], 0.f);
        }
    }

    if constexpr (VW == 4) {
        *reinterpret_cast<float4*>(o0 + (size_t)gw * HD + c0) =
            make_float4(out0[0], out0[1], out0[2], out0[3]);
        *reinterpret_cast<float4*>(o1 + (size_t)gw * HD + c0) =
            make_float4(out1[0], out1[1], out1[2], out1[3]);
    } else {
        *reinterpret_cast<float2*>(o0 + (size_t)gw * HD + c0) =
            make_float2(out0[0], out0[1]);
        *reinterpret_cast<float2*>(o1 + (size_t)gw * HD + c0) =
            make_float2(out1[0], out1[1]);
    }
}

// ---------------- launcher ----------------
extern "C" void kernel_launch(void* const* d_in, const int* in_sizes, int n_in,
                              void* d_out, int out_size)
{
    const float* input = (const float*)d_in[0];
    const int*   src   = (const int*)  d_in[1];
    const int*   dst   = (const int*)  d_in[2];
    const float* W1    = (const float*)d_in[3];
    const float* al1   = (const float*)d_in[4];
    const float* ar1   = (const float*)d_in[5];
    const float* b1    = (const float*)d_in[6];
    const float* W2    = (const float*)d_in[7];
    const float* al2   = (const float*)d_in[8];
    const float* ar2   = (const float*)d_in[9];
    const float* b2    = (const float*)d_in[10];
    const float* W3    = (const float*)d_in[11];
    const float* al3   = (const float*)d_in[12];
    const float* ar3   = (const float*)d_in[13];
    const float* b3    = (const float*)d_in[14];
    float* out = (float*)d_out;

    void *ph, *pel, *per, *py1, *py2;
    cudaGetSymbolAddress(&ph,  g_h);
    cudaGetSymbolAddress(&pel, g_el);
    cudaGetSymbolAddress(&per, g_er);
    cudaGetSymbolAddress(&py1, g_y1);
    cudaGetSymbolAddress(&py2, g_y2);
    __half* hbuf = (__half*)ph;
    float*  elb  = (float*)pel;
    float*  erb  = (float*)per;
    float*  y1   = (float*)py1;
    float*  y2   = (float*)py2;

    // CSR build (edges identical across batches/layers -> build once per launch)
    zero_deg_kernel<<<(NN + 255) / 256, 256>>>();
    hist_kernel<<<(EE + 255) / 256, 256>>>(dst);
    scan_kernel<<<1, 1024>>>();
    scatter_kernel<<<(EE + 255) / 256, 256>>>(src, dst);

    dim3 ggrid((NN + 63) / 64, BB);
    const int agrid = (NN * 32 + 255) / 256;

    // Layer 1: GATConv(64 -> 2 heads x 64)
    gemm_att_kernel<64, 128, 2><<<ggrid, 256>>>(input, (size_t)NN * DIN, W1, al1, ar1, hbuf, elb, erb);
    aggregate_kernel<128, 2, false><<<agrid, 256>>>(hbuf, elb, erb, b1, y1, (size_t)NN * 128);

    // Layer 2: GATConv(128 -> 128, 1 head), ReLU
    gemm_att_kernel<128, 128, 1><<<ggrid, 256>>>(y1, (size_t)NN * 128, W2, al2, ar2, hbuf, elb, erb);
    aggregate_kernel<128, 1, true><<<agrid, 256>>>(hbuf, elb, erb, b2, y2, (size_t)NN * 128);

    // Layer 3: GATConv(128 -> 64, 1 head)
    gemm_att_kernel<128, 64, 1><<<ggrid, 256>>>(y2, (size_t)NN * 128, W3, al3, ar3, hbuf, elb, erb);
    aggregate_kernel<64, 1, false><<<agrid, 256>>>(hbuf, elb, erb, b3, out, (size_t)NN * DOUTC);
}

// round 10
// speedup vs baseline: 2.0125x; 1.8212x over previous
#include <cuda_runtime.h>
#include <cuda_fp16.h>
#include <math.h>

// Problem constants
#define NN    50000
#define EE    800000
#define DIN   64
#define HIDD  128
#define DOUTC 64
#define BB    2

// ---------------- scratch (static device globals; no allocation) ----------------
__device__ __half g_h  [BB * NN * 128];  // projected features (fp16 gather table)
__device__ __half g_x16[BB * NN * 128];  // fp16 GEMM input (converted input / fp16 y)
__device__ __half g_wh [32768];          // W1(8192) | W2(16384) | W3(8192) fp16
__device__ float  g_el [BB * NN * 2];    // per-node attention left  (max 2 heads)
__device__ float  g_er [BB * NN * 2];    // per-node attention right
__device__ int    g_rowptr[NN + 1];      // CSR by dst
__device__ int    g_cursor[NN];          // degree / scatter cursor
__device__ int    g_csrc[EE];            // src per CSR slot

__device__ __forceinline__ unsigned smem_u32(const void* p) {
    return (unsigned)__cvta_generic_to_shared(p);
}

// ---------------- fp16 gather helpers ----------------
__device__ __forceinline__ float4 ldh4(const __half* p) {
    uint2 u = *reinterpret_cast<const uint2*>(p);
    float2 fa = __half22float2(*reinterpret_cast<const __half2*>(&u.x));
    float2 fb = __half22float2(*reinterpret_cast<const __half2*>(&u.y));
    return make_float4(fa.x, fa.y, fb.x, fb.y);
}
__device__ __forceinline__ float2 ldh2(const __half* p) {
    unsigned u = *reinterpret_cast<const unsigned*>(p);
    return __half22float2(*reinterpret_cast<const __half2*>(&u));
}

// ---------------- input / weight conversion ----------------
__global__ void conv_x_kernel(const float* __restrict__ in) {
    int i = blockIdx.x * blockDim.x + threadIdx.x;
    if (i < BB * NN * DIN / 4) {
        float4 v = reinterpret_cast<const float4*>(in)[i];
        union { __half2 h[2]; uint2 u; } cv;
        cv.h[0] = __floats2half2_rn(v.x, v.y);
        cv.h[1] = __floats2half2_rn(v.z, v.w);
        reinterpret_cast<uint2*>(g_x16)[i] = cv.u;
    }
}

__global__ void conv_w_kernel(const float* __restrict__ W1,
                              const float* __restrict__ W2,
                              const float* __restrict__ W3) {
    int i = blockIdx.x * blockDim.x + threadIdx.x;
    if (i < 8192)       g_wh[i] = __float2half_rn(W1[i]);
    else if (i < 24576) g_wh[i] = __float2half_rn(W2[i - 8192]);
    else if (i < 32768) g_wh[i] = __float2half_rn(W3[i - 24576]);
}

// ---------------- CSR build ----------------
__global__ void zero_deg_kernel() {
    int i = blockIdx.x * blockDim.x + threadIdx.x;
    if (i < NN) g_cursor[i] = 0;
}

__global__ void hist_kernel(const int* __restrict__ dst) {
    int e = blockIdx.x * blockDim.x + threadIdx.x;
    if (e < EE) atomicAdd(&g_cursor[dst[e]], 1);
}

__global__ void scan_kernel() {
    __shared__ int ss[1024];
    const int t  = threadIdx.x;
    const int CH = (NN + 1023) / 1024;
    const int b  = t * CH;
    const int e  = min(b + CH, NN);
    int s = 0;
    for (int i = b; i < e; i++) s += g_cursor[i];
    ss[t] = s;
    __syncthreads();
    for (int off = 1; off < 1024; off <<= 1) {
        int v = (t >= off) ? ss[t - off] : 0;
        __syncthreads();
        ss[t] += v;
        __syncthreads();
    }
    int run = (t == 0) ? 0 : ss[t - 1];
    for (int i = b; i < e; i++) {
        int d = g_cursor[i];
        g_rowptr[i] = run;
        g_cursor[i] = run;
        run += d;
    }
    if (t == 1023) g_rowptr[NN] = ss[1023];
}

__global__ void scatter_kernel(const int* __restrict__ src, const int* __restrict__ dst) {
    int e = blockIdx.x * blockDim.x + threadIdx.x;
    if (e < EE) {
        int p = atomicAdd(&g_cursor[dst[e]], 1);
        g_csrc[p] = src[e];
    }
}

// ---------------- HMMA (mma.sync m16n8k16) GEMM + attention epilogue ----------
// Block: 128 threads (4 warps), tile 64 rows x HD. K chunked at 64.
// A = x rows (fp16), B = W [K][HD] row-major (fp16), C fp32.
// Epilogue: h stored fp16, el/er reduced from fp32 accumulators.
template <int K, int HD, int H>
__global__ __launch_bounds__(128) void mma_gemm_att(
    const __half* __restrict__ xbase,
    const __half* __restrict__ Wh,
    const float* __restrict__ al, const float* __restrict__ ar,
    __half* __restrict__ hbase, float* __restrict__ elbase, float* __restrict__ erbase)
{
    constexpr int KS = 64;
    constexpr int PX = KS + 8;     // xs pitch in halves (144B rows: conflict-free LDSM)
    constexpr int PW = HD + 8;     // ws pitch in halves
    constexpr int NT = HD / 8;     // n-tiles of 8 cols
    constexpr int D  = HD / H;

    __shared__ __align__(16) __half xs[64 * PX];
    __shared__ __align__(16) __half ws[KS * PW];
    __shared__ float sal[HD], sar[HD];

    const __half* x    = xbase + (size_t)blockIdx.y * NN * K;
    __half*       hout = hbase + (size_t)blockIdx.y * NN * HD;
    float*        el   = elbase + (size_t)blockIdx.y * NN * H;
    float*        er   = erbase + (size_t)blockIdx.y * NN * H;

    const int tid  = threadIdx.x;
    const int warp = tid >> 5;
    const int lane = tid & 31;
    const int g    = lane >> 2;
    const int t    = lane & 3;
    const int row0 = blockIdx.x * 64;

    for (int i = tid; i < HD; i += 128) { sal[i] = al[i]; sar[i] = ar[i]; }

    float C[NT][4];
    #pragma unroll
    for (int j = 0; j < NT; j++)
        #pragma unroll
        for (int c = 0; c < 4; c++) C[j][c] = 0.f;

    for (int ko = 0; ko < K; ko += KS) {
        // ---- load x tile: 64 rows x KS halves ----
        for (int idx = tid; idx < 64 * (KS / 8); idx += 128) {
            int r = idx / (KS / 8), j = idx % (KS / 8);
            int grow = min(row0 + r, NN - 1);
            *reinterpret_cast<uint4*>(&xs[r * PX + j * 8]) =
                *reinterpret_cast<const uint4*>(&x[(size_t)grow * K + ko + j * 8]);
        }
        // ---- load W tile: KS rows x HD halves ----
        for (int idx = tid; idx < KS * (HD / 8); idx += 128) {
            int r = idx / (HD / 8), j = idx % (HD / 8);
            *reinterpret_cast<uint4*>(&ws[r * PW + j * 8]) =
                *reinterpret_cast<const uint4*>(&Wh[(size_t)(ko + r) * HD + j * 8]);
        }
        __syncthreads();

        #pragma unroll
        for (int kk = 0; kk < KS; kk += 16) {
            // A fragments: ldmatrix x4 (m0: rows0-7 k0-7, m1: rows8-15 k0-7,
            //                           m2: rows0-7 k8-15, m3: rows8-15 k8-15)
            unsigned a0, a1, a2, a3;
            {
                int i8  = lane & 7;
                int sel = lane >> 3;
                int arow = warp * 16 + i8 + (sel & 1) * 8;
                int akk  = kk + (sel >> 1) * 8;
                unsigned addr = smem_u32(&xs[arow * PX + akk]);
                asm volatile("ldmatrix.sync.aligned.m8n8.x4.shared.b16 {%0,%1,%2,%3}, [%4];"
                             : "=r"(a0), "=r"(a1), "=r"(a2), "=r"(a3) : "r"(addr));
            }
            #pragma unroll
            for (int j = 0; j < NT; j++) {
                unsigned b0, b1;
                int i8 = lane & 7;
                int s  = (lane >> 3) & 1;
                unsigned baddr = smem_u32(&ws[(kk + s * 8 + i8) * PW + j * 8]);
                asm volatile("ldmatrix.sync.aligned.m8n8.x2.trans.shared.b16 {%0,%1}, [%2];"
                             : "=r"(b0), "=r"(b1) : "r"(baddr));
                asm volatile("mma.sync.aligned.m16n8k16.row.col.f32.f16.f16.f32 "
                             "{%0,%1,%2,%3}, {%4,%5,%6,%7}, {%8,%9}, {%0,%1,%2,%3};"
                             : "+f"(C[j][0]), "+f"(C[j][1]), "+f"(C[j][2]), "+f"(C[j][3])
                             : "r"(a0), "r"(a1), "r"(a2), "r"(a3), "r"(b0), "r"(b1));
            }
        }
        __syncthreads();
    }

    // ---- epilogue: store h fp16, accumulate el/er ----
    const int row_a = row0 + warp * 16 + g;
    const int row_b = row_a + 8;

    float pelA[H], perA[H], pelB[H], perB[H];
    #pragma unroll
    for (int h = 0; h < H; h++) { pelA[h] = 0.f; perA[h] = 0.f; pelB[h] = 0.f; perB[h] = 0.f; }

    #pragma unroll
    for (int j = 0; j < NT; j++) {
        const int cc = j * 8 + 2 * t;
        const int hh = (j * 8) / D;
        const float a0v = sal[cc], a1v = sal[cc + 1];
        const float r0v = sar[cc], r1v = sar[cc + 1];
        pelA[hh] = fmaf(C[j][0], a0v, fmaf(C[j][1], a1v, pelA[hh]));
        perA[hh] = fmaf(C[j][0], r0v, fmaf(C[j][1], r1v, perA[hh]));
        pelB[hh] = fmaf(C[j][2], a0v, fmaf(C[j][3], a1v, pelB[hh]));
        perB[hh] = fmaf(C[j][2], r0v, fmaf(C[j][3], r1v, perB[hh]));
        if (row_a < NN) {
            __half2 hv = __floats2half2_rn(C[j][0], C[j][1]);
            *reinterpret_cast<unsigned*>(&hout[(size_t)row_a * HD + cc]) =
                *reinterpret_cast<unsigned*>(&hv);
        }
        if (row_b < NN) {
            __half2 hv = __floats2half2_rn(C[j][2], C[j][3]);
            *reinterpret_cast<unsigned*>(&hout[(size_t)row_b * HD + cc]) =
                *reinterpret_cast<unsigned*>(&hv);
        }
    }

    // reduce across the 4 lanes (t = 0..3) sharing each row
    #pragma unroll
    for (int h = 0; h < H; h++) {
        pelA[h] += __shfl_xor_sync(0xffffffffu, pelA[h], 1);
        pelA[h] += __shfl_xor_sync(0xffffffffu, pelA[h], 2);
        perA[h] += __shfl_xor_sync(0xffffffffu, perA[h], 1);
        perA[h] += __shfl_xor_sync(0xffffffffu, perA[h], 2);
        pelB[h] += __shfl_xor_sync(0xffffffffu, pelB[h], 1);
        pelB[h] += __shfl_xor_sync(0xffffffffu, pelB[h], 2);
        perB[h] += __shfl_xor_sync(0xffffffffu, perB[h], 1);
        perB[h] += __shfl_xor_sync(0xffffffffu, perB[h], 2);
    }
    if (t == 0) {
        #pragma unroll
        for (int h = 0; h < H; h++) {
            if (row_a < NN) { el[row_a * H + h] = pelA[h]; er[row_a * H + h] = perA[h]; }
            if (row_b < NN) { el[row_b * H + h] = pelB[h]; er[row_b * H + h] = perB[h]; }
        }
    }
}

// ---------------- fused edge-softmax + aggregation, BOTH batches per warp ----
// R7 structure (proven): in-loop exp, 2-edge unroll, node-per-warp, fp16 h gathers.
// OT = __half (intermediate y) or float (final output).
template <int HD, int H, bool RELU, typename OT>
__global__ __launch_bounds__(256) void aggregate_kernel(
    const __half* __restrict__ hbase, const float* __restrict__ elbase,
    const float* __restrict__ erbase, const float* __restrict__ bias,
    OT* __restrict__ outbase, size_t outstride)
{
    constexpr int VW = HD / 32;
    constexpr int D  = HD / H;

    const __half* h0  = hbase;
    const __half* h1  = hbase  + (size_t)NN * HD;
    const float*  el0 = elbase;
    const float*  el1 = elbase + (size_t)NN * H;
    const float*  er0 = erbase;
    const float*  er1 = erbase + (size_t)NN * H;
    OT*           o0  = outbase;
    OT*           o1  = outbase + outstride;

    const int gw   = (blockIdx.x * blockDim.x + threadIdx.x) >> 5;
    const int lane = threadIdx.x & 31;
    if (gw >= NN) return;

    const int s0 = g_rowptr[gw];
    const int s1 = g_rowptr[gw + 1];
    const int c0 = lane * VW;
    const int hl = c0 / D;

    const float erA = er0[gw * H + hl];
    const float erB = er1[gw * H + hl];

    float acc0[VW], acc1[VW];
    #pragma unroll
    for (int j = 0; j < VW; j++) { acc0[j] = 0.f; acc1[j] = 0.f; }
    float sum0 = 0.f, sum1 = 0.f;

    int e = s0;
    for (; e + 1 < s1; e += 2) {
        const int sA = g_csrc[e];
        const int sB = g_csrc[e + 1];
        const float ea0 = el0[sA * H + hl];
        const float ea1 = el1[sA * H + hl];
        const float eb0 = el0[sB * H + hl];
        const float eb1 = el1[sB * H + hl];
        const __half* pa0 = h0 + (size_t)sA * HD + c0;
        const __half* pa1 = h1 + (size_t)sA * HD + c0;
        const __half* pb0 = h0 + (size_t)sB * HD + c0;
        const __half* pb1 = h1 + (size_t)sB * HD + c0;

        float va0 = ea0 + erA; va0 = (va0 > 0.f) ? va0 : 0.2f * va0;
        float va1 = ea1 + erB; va1 = (va1 > 0.f) ? va1 : 0.2f * va1;
        float vb0 = eb0 + erA; vb0 = (vb0 > 0.f) ? vb0 : 0.2f * vb0;
        float vb1 = eb1 + erB; vb1 = (vb1 > 0.f) ? vb1 : 0.2f * vb1;
        const float wa0 = __expf(va0);
        const float wa1 = __expf(va1);
        const float wb0 = __expf(vb0);
        const float wb1 = __expf(vb1);
        sum0 += wa0 + wb0;
        sum1 += wa1 + wb1;

        if constexpr (VW == 4) {
            float4 A0 = ldh4(pa0);
            float4 A1 = ldh4(pa1);
            float4 B0 = ldh4(pb0);
            float4 B1 = ldh4(pb1);
            acc0[0] = fmaf(wa0, A0.x, acc0[0]); acc0[0] = fmaf(wb0, B0.x, acc0[0]);
            acc0[1] = fmaf(wa0, A0.y, acc0[1]); acc0[1] = fmaf(wb0, B0.y, acc0[1]);
            acc0[2] = fmaf(wa0, A0.z, acc0[2]); acc0[2] = fmaf(wb0, B0.z, acc0[2]);
            acc0[3] = fmaf(wa0, A0.w, acc0[3]); acc0[3] = fmaf(wb0, B0.w, acc0[3]);
            acc1[0] = fmaf(wa1, A1.x, acc1[0]); acc1[0] = fmaf(wb1, B1.x, acc1[0]);
            acc1[1] = fmaf(wa1, A1.y, acc1[1]); acc1[1] = fmaf(wb1, B1.y, acc1[1]);
            acc1[2] = fmaf(wa1, A1.z, acc1[2]); acc1[2] = fmaf(wb1, B1.z, acc1[2]);
            acc1[3] = fmaf(wa1, A1.w, acc1[3]); acc1[3] = fmaf(wb1, B1.w, acc1[3]);
        } else {
            float2 A0 = ldh2(pa0);
            float2 A1 = ldh2(pa1);
            float2 B0 = ldh2(pb0);
            float2 B1 = ldh2(pb1);
            acc0[0] = fmaf(wa0, A0.x, acc0[0]); acc0[0] = fmaf(wb0, B0.x, acc0[0]);
            acc0[1] = fmaf(wa0, A0.y, acc0[1]); acc0[1] = fmaf(wb0, B0.y, acc0[1]);
            acc1[0] = fmaf(wa1, A1.x, acc1[0]); acc1[0] = fmaf(wb1, B1.x, acc1[0]);
            acc1[1] = fmaf(wa1, A1.y, acc1[1]); acc1[1] = fmaf(wb1, B1.y, acc1[1]);
        }
    }
    if (e < s1) {
        const int sA = g_csrc[e];
        const float ea0 = el0[sA * H + hl];
        const float ea1 = el1[sA * H + hl];
        float va0 = ea0 + erA; va0 = (va0 > 0.f) ? va0 : 0.2f * va0;
        float va1 = ea1 + erB; va1 = (va1 > 0.f) ? va1 : 0.2f * va1;
        const float wa0 = __expf(va0);
        const float wa1 = __expf(va1);
        sum0 += wa0;
        sum1 += wa1;
        const __half* pa0 = h0 + (size_t)sA * HD + c0;
        const __half* pa1 = h1 + (size_t)sA * HD + c0;
        if constexpr (VW == 4) {
            float4 A0 = ldh4(pa0);
            float4 A1 = ldh4(pa1);
            acc0[0] = fmaf(wa0, A0.x, acc0[0]);
            acc0[1] = fmaf(wa0, A0.y, acc0[1]);
            acc0[2] = fmaf(wa0, A0.z, acc0[2]);
            acc0[3] = fmaf(wa0, A0.w, acc0[3]);
            acc1[0] = fmaf(wa1, A1.x, acc1[0]);
            acc1[1] = fmaf(wa1, A1.y, acc1[1]);
            acc1[2] = fmaf(wa1, A1.z, acc1[2]);
            acc1[3] = fmaf(wa1, A1.w, acc1[3]);
        } else {
            float2 A0 = ldh2(pa0);
            float2 A1 = ldh2(pa1);
            acc0[0] = fmaf(wa0, A0.x, acc0[0]);
            acc0[1] = fmaf(wa0, A0.y, acc0[1]);
            acc1[0] = fmaf(wa1, A1.x, acc1[0]);
            acc1[1] = fmaf(wa1, A1.y, acc1[1]);
        }
    }

    float bv[VW];
    #pragma unroll
    for (int j = 0; j < VW; j++) bv[j] = bias[c0 + j];

    float out0[VW], out1[VW];
    if (s1 > s0) {
        const float i0 = 1.f / sum0;
        const float i1 = 1.f / sum1;
        #pragma unroll
        for (int j = 0; j < VW; j++) {
            out0[j] = fmaf(acc0[j], i0, bv[j]);
            out1[j] = fmaf(acc1[j], i1, bv[j]);
        }
    } else {
        #pragma unroll
        for (int j = 0; j < VW; j++) { out0[j] = bv[j]; out1[j] = bv[j]; }
    }
    if (RELU) {
        #pragma unroll
        for (int j = 0; j < VW; j++) {
            out0[j] = fmaxf(out0[j], 0.f);
            out1[j] = fmaxf(out1[j], 0.f);
        }
    }

    if constexpr (sizeof(OT) == 2) {
        if constexpr (VW == 4) {
            union { __half2 h[2]; uint2 u; } cv0, cv1;
            cv0.h[0] = __floats2half2_rn(out0[0], out0[1]);
            cv0.h[1] = __floats2half2_rn(out0[2], out0[3]);
            cv1.h[0] = __floats2half2_rn(out1[0], out1[1]);
            cv1.h[1] = __floats2half2_rn(out1[2], out1[3]);
            *reinterpret_cast<uint2*>(o0 + (size_t)gw * HD + c0) = cv0.u;
            *reinterpret_cast<uint2*>(o1 + (size_t)gw * HD + c0) = cv1.u;
        } else {
            __half2 v0 = __floats2half2_rn(out0[0], out0[1]);
            __half2 v1 = __floats2half2_rn(out1[0], out1[1]);
            *reinterpret_cast<unsigned*>(o0 + (size_t)gw * HD + c0) =
                *reinterpret_cast<unsigned*>(&v0);
            *reinterpret_cast<unsigned*>(o1 + (size_t)gw * HD + c0) =
                *reinterpret_cast<unsigned*>(&v1);
        }
    } else {
        if constexpr (VW == 4) {
            *reinterpret_cast<float4*>(o0 + (size_t)gw * HD + c0) =
                make_float4(out0[0], out0[1], out0[2], out0[3]);
            *reinterpret_cast<float4*>(o1 + (size_t)gw * HD + c0) =
                make_float4(out1[0], out1[1], out1[2], out1[3]);
        } else {
            *reinterpret_cast<float2*>(o0 + (size_t)gw * HD + c0) =
                make_float2(out0[0], out0[1]);
            *reinterpret_cast<float2*>(o1 + (size_t)gw * HD + c0) =
                make_float2(out1[0], out1[1]);
        }
    }
}

// ---------------- launcher ----------------
extern "C" void kernel_launch(void* const* d_in, const int* in_sizes, int n_in,
                              void* d_out, int out_size)
{
    const float* input = (const float*)d_in[0];
    const int*   src   = (const int*)  d_in[1];
    const int*   dst   = (const int*)  d_in[2];
    const float* W1    = (const float*)d_in[3];
    const float* al1   = (const float*)d_in[4];
    const float* ar1   = (const float*)d_in[5];
    const float* b1    = (const float*)d_in[6];
    const float* W2    = (const float*)d_in[7];
    const float* al2   = (const float*)d_in[8];
    const float* ar2   = (const float*)d_in[9];
    const float* b2    = (const float*)d_in[10];
    const float* W3    = (const float*)d_in[11];
    const float* al3   = (const float*)d_in[12];
    const float* ar3   = (const float*)d_in[13];
    const float* b3    = (const float*)d_in[14];
    float* out = (float*)d_out;

    void *ph, *px, *pw, *pel, *per;
    cudaGetSymbolAddress(&ph,  g_h);
    cudaGetSymbolAddress(&px,  g_x16);
    cudaGetSymbolAddress(&pw,  g_wh);
    cudaGetSymbolAddress(&pel, g_el);
    cudaGetSymbolAddress(&per, g_er);
    __half* hbuf = (__half*)ph;
    __half* x16  = (__half*)px;
    __half* wh   = (__half*)pw;
    float*  elb  = (float*)pel;
    float*  erb  = (float*)per;

    // conversions + CSR build
    conv_x_kernel<<<(BB * NN * DIN / 4 + 255) / 256, 256>>>(input);
    conv_w_kernel<<<(32768 + 255) / 256, 256>>>(W1, W2, W3);
    zero_deg_kernel<<<(NN + 255) / 256, 256>>>();
    hist_kernel<<<(EE + 255) / 256, 256>>>(dst);
    scan_kernel<<<1, 1024>>>();
    scatter_kernel<<<(EE + 255) / 256, 256>>>(src, dst);

    dim3 ggrid((NN + 63) / 64, BB);
    const int agrid = (NN * 32 + 255) / 256;

    // Layer 1: GATConv(64 -> 2 heads x 64)
    mma_gemm_att<64, 128, 2><<<ggrid, 128>>>(x16, wh, al1, ar1, hbuf, elb, erb);
    aggregate_kernel<128, 2, false, __half><<<agrid, 256>>>(hbuf, elb, erb, b1, x16, (size_t)NN * 128);

    // Layer 2: GATConv(128 -> 128, 1 head), ReLU
    mma_gemm_att<128, 128, 1><<<ggrid, 128>>>(x16, wh + 8192, al2, ar2, hbuf, elb, erb);
    aggregate_kernel<128, 1, true, __half><<<agrid, 256>>>(hbuf, elb, erb, b2, x16, (size_t)NN * 128);

    // Layer 3: GATConv(128 -> 64, 1 head)
    mma_gemm_att<128, 64, 1><<<ggrid, 128>>>(x16, wh + 24576, al3, ar3, hbuf, elb, erb);
    aggregate_kernel<64, 1, false, float><<<agrid, 256>>>(hbuf, elb, erb, b3, out, (size_t)NN * DOUTC);
}

// round 11
// speedup vs baseline: 2.0245x; 1.0059x over previous
#include <cuda_runtime.h>
#include <cuda_fp16.h>
#include <math.h>

// Problem constants
#define NN    50000
#define EE    800000
#define DIN   64
#define HIDD  128
#define DOUTC 64
#define BB    2

// ---------------- scratch (static device globals; no allocation) ----------------
// g_h layout is BATCH-INTERLEAVED per node: for HD features and VW=HD/32,
// node row = 2*HD halves as 32 chunks of 2*VW halves: [b0 feats VW*j..][b1 feats VW*j..]
__device__ __half g_h  [BB * NN * 128];  // projected features (interleaved gather table)
__device__ __half g_x16[BB * NN * 128];  // fp16 GEMM input (converted input / fp16 y), batch-major
__device__ __half g_wh [32768];          // W1(8192) | W2(16384) | W3(8192) fp16
__device__ float  g_el [BB * NN * 2];    // per-node attention left  (max 2 heads)
__device__ float  g_er [BB * NN * 2];    // per-node attention right
__device__ int    g_rowptr[NN + 1];      // CSR by dst
__device__ int    g_cursor[NN];          // degree / scatter cursor
__device__ int    g_csrc[EE];            // src per CSR slot

__device__ __forceinline__ unsigned smem_u32(const void* p) {
    return (unsigned)__cvta_generic_to_shared(p);
}

__device__ __forceinline__ float2 h2f(unsigned u) {
    return __half22float2(*reinterpret_cast<const __half2*>(&u));
}

// ---------------- input / weight conversion ----------------
__global__ void conv_x_kernel(const float* __restrict__ in) {
    int i = blockIdx.x * blockDim.x + threadIdx.x;
    if (i < BB * NN * DIN / 4) {
        float4 v = reinterpret_cast<const float4*>(in)[i];
        union { __half2 h[2]; uint2 u; } cv;
        cv.h[0] = __floats2half2_rn(v.x, v.y);
        cv.h[1] = __floats2half2_rn(v.z, v.w);
        reinterpret_cast<uint2*>(g_x16)[i] = cv.u;
    }
}

__global__ void conv_w_kernel(const float* __restrict__ W1,
                              const float* __restrict__ W2,
                              const float* __restrict__ W3) {
    int i = blockIdx.x * blockDim.x + threadIdx.x;
    if (i < 8192)       g_wh[i] = __float2half_rn(W1[i]);
    else if (i < 24576) g_wh[i] = __float2half_rn(W2[i - 8192]);
    else if (i < 32768) g_wh[i] = __float2half_rn(W3[i - 24576]);
}

// ---------------- CSR build ----------------
__global__ void zero_deg_kernel() {
    int i = blockIdx.x * blockDim.x + threadIdx.x;
    if (i < NN) g_cursor[i] = 0;
}

__global__ void hist_kernel(const int* __restrict__ dst) {
    int e = blockIdx.x * blockDim.x + threadIdx.x;
    if (e < EE) atomicAdd(&g_cursor[dst[e]], 1);
}

__global__ void scan_kernel() {
    __shared__ int ss[1024];
    const int t  = threadIdx.x;
    const int CH = (NN + 1023) / 1024;
    const int b  = t * CH;
    const int e  = min(b + CH, NN);
    int s = 0;
    for (int i = b; i < e; i++) s += g_cursor[i];
    ss[t] = s;
    __syncthreads();
    for (int off = 1; off < 1024; off <<= 1) {
        int v = (t >= off) ? ss[t - off] : 0;
        __syncthreads();
        ss[t] += v;
        __syncthreads();
    }
    int run = (t == 0) ? 0 : ss[t - 1];
    for (int i = b; i < e; i++) {
        int d = g_cursor[i];
        g_rowptr[i] = run;
        g_cursor[i] = run;
        run += d;
    }
    if (t == 1023) g_rowptr[NN] = ss[1023];
}

__global__ void scatter_kernel(const int* __restrict__ src, const int* __restrict__ dst) {
    int e = blockIdx.x * blockDim.x + threadIdx.x;
    if (e < EE) {
        int p = atomicAdd(&g_cursor[dst[e]], 1);
        g_csrc[p] = src[e];
    }
}

// ---------------- HMMA (mma.sync m16n8k16) GEMM + attention epilogue ----------
// Block: 128 threads (4 warps), tile 64 rows x HD. K chunked at 64.
// Epilogue stores h fp16 into the BATCH-INTERLEAVED layout; el/er from fp32 accs.
template <int K, int HD, int H>
__global__ __launch_bounds__(128) void mma_gemm_att(
    const __half* __restrict__ xbase,
    const __half* __restrict__ Wh,
    const float* __restrict__ al, const float* __restrict__ ar,
    __half* __restrict__ hbase, float* __restrict__ elbase, float* __restrict__ erbase)
{
    constexpr int KS = 64;
    constexpr int PX = KS + 8;
    constexpr int PW = HD + 8;
    constexpr int NT = HD / 8;
    constexpr int D  = HD / H;
    constexpr int VW = HD / 32;    // interleave chunk = VW feats per batch

    __shared__ __align__(16) __half xs[64 * PX];
    __shared__ __align__(16) __half ws[KS * PW];
    __shared__ float sal[HD], sar[HD];

    const int bb = blockIdx.y;
    const __half* x  = xbase + (size_t)bb * NN * K;
    float*        el = elbase + (size_t)bb * NN * H;
    float*        er = erbase + (size_t)bb * NN * H;

    const int tid  = threadIdx.x;
    const int warp = tid >> 5;
    const int lane = tid & 31;
    const int g    = lane >> 2;
    const int t    = lane & 3;
    const int row0 = blockIdx.x * 64;

    for (int i = tid; i < HD; i += 128) { sal[i] = al[i]; sar[i] = ar[i]; }

    float C[NT][4];
    #pragma unroll
    for (int j = 0; j < NT; j++)
        #pragma unroll
        for (int c = 0; c < 4; c++) C[j][c] = 0.f;

    for (int ko = 0; ko < K; ko += KS) {
        for (int idx = tid; idx < 64 * (KS / 8); idx += 128) {
            int r = idx / (KS / 8), j = idx % (KS / 8);
            int grow = min(row0 + r, NN - 1);
            *reinterpret_cast<uint4*>(&xs[r * PX + j * 8]) =
                *reinterpret_cast<const uint4*>(&x[(size_t)grow * K + ko + j * 8]);
        }
        for (int idx = tid; idx < KS * (HD / 8); idx += 128) {
            int r = idx / (HD / 8), j = idx % (HD / 8);
            *reinterpret_cast<uint4*>(&ws[r * PW + j * 8]) =
                *reinterpret_cast<const uint4*>(&Wh[(size_t)(ko + r) * HD + j * 8]);
        }
        __syncthreads();

        #pragma unroll
        for (int kk = 0; kk < KS; kk += 16) {
            unsigned a0, a1, a2, a3;
            {
                int i8  = lane & 7;
                int sel = lane >> 3;
                int arow = warp * 16 + i8 + (sel & 1) * 8;
                int akk  = kk + (sel >> 1) * 8;
                unsigned addr = smem_u32(&xs[arow * PX + akk]);
                asm volatile("ldmatrix.sync.aligned.m8n8.x4.shared.b16 {%0,%1,%2,%3}, [%4];"
                             : "=r"(a0), "=r"(a1), "=r"(a2), "=r"(a3) : "r"(addr));
            }
            #pragma unroll
            for (int j = 0; j < NT; j++) {
                unsigned b0, b1;
                int i8 = lane & 7;
                int s  = (lane >> 3) & 1;
                unsigned baddr = smem_u32(&ws[(kk + s * 8 + i8) * PW + j * 8]);
                asm volatile("ldmatrix.sync.aligned.m8n8.x2.trans.shared.b16 {%0,%1}, [%2];"
                             : "=r"(b0), "=r"(b1) : "r"(baddr));
                asm volatile("mma.sync.aligned.m16n8k16.row.col.f32.f16.f16.f32 "
                             "{%0,%1,%2,%3}, {%4,%5,%6,%7}, {%8,%9}, {%0,%1,%2,%3};"
                             : "+f"(C[j][0]), "+f"(C[j][1]), "+f"(C[j][2]), "+f"(C[j][3])
                             : "r"(a0), "r"(a1), "r"(a2), "r"(a3), "r"(b0), "r"(b1));
            }
        }
        __syncthreads();
    }

    // ---- epilogue: store h fp16 (interleaved layout), accumulate el/er ----
    const int row_a = row0 + warp * 16 + g;
    const int row_b = row_a + 8;

    float pelA[H], perA[H], pelB[H], perB[H];
    #pragma unroll
    for (int h = 0; h < H; h++) { pelA[h] = 0.f; perA[h] = 0.f; pelB[h] = 0.f; perB[h] = 0.f; }

    #pragma unroll
    for (int j = 0; j < NT; j++) {
        const int cc = j * 8 + 2 * t;
        const int hh = (j * 8) / D;
        const float a0v = sal[cc], a1v = sal[cc + 1];
        const float r0v = sar[cc], r1v = sar[cc + 1];
        pelA[hh] = fmaf(C[j][0], a0v, fmaf(C[j][1], a1v, pelA[hh]));
        perA[hh] = fmaf(C[j][0], r0v, fmaf(C[j][1], r1v, perA[hh]));
        pelB[hh] = fmaf(C[j][2], a0v, fmaf(C[j][3], a1v, pelB[hh]));
        perB[hh] = fmaf(C[j][2], r0v, fmaf(C[j][3], r1v, perB[hh]));
        // interleaved address: node*(2*HD) + (cc/VW)*(2*VW) + b*VW + (cc%VW)
        const int ioff = (cc / VW) * (2 * VW) + bb * VW + (cc % VW);
        if (row_a < NN) {
            __half2 hv = __floats2half2_rn(C[j][0], C[j][1]);
            *reinterpret_cast<unsigned*>(&hbase[(size_t)row_a * (2 * HD) + ioff]) =
                *reinterpret_cast<unsigned*>(&hv);
        }
        if (row_b < NN) {
            __half2 hv = __floats2half2_rn(C[j][2], C[j][3]);
            *reinterpret_cast<unsigned*>(&hbase[(size_t)row_b * (2 * HD) + ioff]) =
                *reinterpret_cast<unsigned*>(&hv);
        }
    }

    #pragma unroll
    for (int h = 0; h < H; h++) {
        pelA[h] += __shfl_xor_sync(0xffffffffu, pelA[h], 1);
        pelA[h] += __shfl_xor_sync(0xffffffffu, pelA[h], 2);
        perA[h] += __shfl_xor_sync(0xffffffffu, perA[h], 1);
        perA[h] += __shfl_xor_sync(0xffffffffu, perA[h], 2);
        pelB[h] += __shfl_xor_sync(0xffffffffu, pelB[h], 1);
        pelB[h] += __shfl_xor_sync(0xffffffffu, pelB[h], 2);
        perB[h] += __shfl_xor_sync(0xffffffffu, perB[h], 1);
        perB[h] += __shfl_xor_sync(0xffffffffu, perB[h], 2);
    }
    if (t == 0) {
        #pragma unroll
        for (int h = 0; h < H; h++) {
            if (row_a < NN) { el[row_a * H + h] = pelA[h]; er[row_a * H + h] = perA[h]; }
            if (row_b < NN) { el[row_b * H + h] = pelB[h]; er[row_b * H + h] = perB[h]; }
        }
    }
}

// ---------------- fused edge-softmax + aggregation, BOTH batches per warp ----
// Interleaved h: ONE gather per edge fetches both batches (16 B/lane for HD=128).
template <int HD, int H, bool RELU, typename OT>
__global__ __launch_bounds__(256) void aggregate_kernel(
    const __half* __restrict__ hbase, const float* __restrict__ elbase,
    const float* __restrict__ erbase, const float* __restrict__ bias,
    OT* __restrict__ outbase, size_t outstride)
{
    constexpr int VW = HD / 32;
    constexpr int D  = HD / H;

    const float*  el0 = elbase;
    const float*  el1 = elbase + (size_t)NN * H;
    const float*  er0 = erbase;
    const float*  er1 = erbase + (size_t)NN * H;
    OT*           o0  = outbase;
    OT*           o1  = outbase + outstride;

    const int gw   = (blockIdx.x * blockDim.x + threadIdx.x) >> 5;
    const int lane = threadIdx.x & 31;
    if (gw >= NN) return;

    const int s0 = g_rowptr[gw];
    const int s1 = g_rowptr[gw + 1];
    const int c0 = lane * VW;
    const int hl = c0 / D;
    const int loff = lane * (2 * VW);   // lane offset within interleaved node row

    const float erA = er0[gw * H + hl];
    const float erB = er1[gw * H + hl];

    float acc0[VW], acc1[VW];
    #pragma unroll
    for (int j = 0; j < VW; j++) { acc0[j] = 0.f; acc1[j] = 0.f; }
    float sum0 = 0.f, sum1 = 0.f;

    int e = s0;
    for (; e + 1 < s1; e += 2) {
        const int sA = g_csrc[e];
        const int sB = g_csrc[e + 1];
        const float ea0 = el0[sA * H + hl];
        const float ea1 = el1[sA * H + hl];
        const float eb0 = el0[sB * H + hl];
        const float eb1 = el1[sB * H + hl];
        const __half* pA = hbase + (size_t)sA * (2 * HD) + loff;
        const __half* pB = hbase + (size_t)sB * (2 * HD) + loff;

        float va0 = ea0 + erA; va0 = (va0 > 0.f) ? va0 : 0.2f * va0;
        float va1 = ea1 + erB; va1 = (va1 > 0.f) ? va1 : 0.2f * va1;
        float vb0 = eb0 + erA; vb0 = (vb0 > 0.f) ? vb0 : 0.2f * vb0;
        float vb1 = eb1 + erB; vb1 = (vb1 > 0.f) ? vb1 : 0.2f * vb1;
        const float wa0 = __expf(va0);
        const float wa1 = __expf(va1);
        const float wb0 = __expf(vb0);
        const float wb1 = __expf(vb1);
        sum0 += wa0 + wb0;
        sum1 += wa1 + wb1;

        if constexpr (VW == 4) {
            uint4 uA = *reinterpret_cast<const uint4*>(pA);
            uint4 uB = *reinterpret_cast<const uint4*>(pB);
            float2 A0a = h2f(uA.x), A0b = h2f(uA.y);  // batch0 feats
            float2 A1a = h2f(uA.z), A1b = h2f(uA.w);  // batch1 feats
            float2 B0a = h2f(uB.x), B0b = h2f(uB.y);
            float2 B1a = h2f(uB.z), B1b = h2f(uB.w);
            acc0[0] = fmaf(wa0, A0a.x, acc0[0]); acc0[0] = fmaf(wb0, B0a.x, acc0[0]);
            acc0[1] = fmaf(wa0, A0a.y, acc0[1]); acc0[1] = fmaf(wb0, B0a.y, acc0[1]);
            acc0[2] = fmaf(wa0, A0b.x, acc0[2]); acc0[2] = fmaf(wb0, B0b.x, acc0[2]);
            acc0[3] = fmaf(wa0, A0b.y, acc0[3]); acc0[3] = fmaf(wb0, B0b.y, acc0[3]);
            acc1[0] = fmaf(wa1, A1a.x, acc1[0]); acc1[0] = fmaf(wb1, B1a.x, acc1[0]);
            acc1[1] = fmaf(wa1, A1a.y, acc1[1]); acc1[1] = fmaf(wb1, B1a.y, acc1[1]);
            acc1[2] = fmaf(wa1, A1b.x, acc1[2]); acc1[2] = fmaf(wb1, B1b.x, acc1[2]);
            acc1[3] = fmaf(wa1, A1b.y, acc1[3]); acc1[3] = fmaf(wb1, B1b.y, acc1[3]);
        } else {
            uint2 uA = *reinterpret_cast<const uint2*>(pA);
            uint2 uB = *reinterpret_cast<const uint2*>(pB);
            float2 A0 = h2f(uA.x), A1 = h2f(uA.y);
            float2 B0 = h2f(uB.x), B1 = h2f(uB.y);
            acc0[0] = fmaf(wa0, A0.x, acc0[0]); acc0[0] = fmaf(wb0, B0.x, acc0[0]);
            acc0[1] = fmaf(wa0, A0.y, acc0[1]); acc0[1] = fmaf(wb0, B0.y, acc0[1]);
            acc1[0] = fmaf(wa1, A1.x, acc1[0]); acc1[0] = fmaf(wb1, B1.x, acc1[0]);
            acc1[1] = fmaf(wa1, A1.y, acc1[1]); acc1[1] = fmaf(wb1, B1.y, acc1[1]);
        }
    }
    if (e < s1) {
        const int sA = g_csrc[e];
        const float ea0 = el0[sA * H + hl];
        const float ea1 = el1[sA * H + hl];
        float va0 = ea0 + erA; va0 = (va0 > 0.f) ? va0 : 0.2f * va0;
        float va1 = ea1 + erB; va1 = (va1 > 0.f) ? va1 : 0.2f * va1;
        const float wa0 = __expf(va0);
        const float wa1 = __expf(va1);
        sum0 += wa0;
        sum1 += wa1;
        const __half* pA = hbase + (size_t)sA * (2 * HD) + loff;
        if constexpr (VW == 4) {
            uint4 uA = *reinterpret_cast<const uint4*>(pA);
            float2 A0a = h2f(uA.x), A0b = h2f(uA.y);
            float2 A1a = h2f(uA.z), A1b = h2f(uA.w);
            acc0[0] = fmaf(wa0, A0a.x, acc0[0]);
            acc0[1] = fmaf(wa0, A0a.y, acc0[1]);
            acc0[2] = fmaf(wa0, A0b.x, acc0[2]);
            acc0[3] = fmaf(wa0, A0b.y, acc0[3]);
            acc1[0] = fmaf(wa1, A1a.x, acc1[0]);
            acc1[1] = fmaf(wa1, A1a.y, acc1[1]);
            acc1[2] = fmaf(wa1, A1b.x, acc1[2]);
            acc1[3] = fmaf(wa1, A1b.y, acc1[3]);
        } else {
            uint2 uA = *reinterpret_cast<const uint2*>(pA);
            float2 A0 = h2f(uA.x), A1 = h2f(uA.y);
            acc0[0] = fmaf(wa0, A0.x, acc0[0]);
            acc0[1] = fmaf(wa0, A0.y, acc0[1]);
            acc1[0] = fmaf(wa1, A1.x, acc1[0]);
            acc1[1] = fmaf(wa1, A1.y, acc1[1]);
        }
    }

    float bv[VW];
    #pragma unroll
    for (int j = 0; j < VW; j++) bv[j] = bias[c0 + j];

    float out0[VW], out1[VW];
    if (s1 > s0) {
        const float i0 = 1.f / sum0;
        const float i1 = 1.f / sum1;
        #pragma unroll
        for (int j = 0; j < VW; j++) {
            out0[j] = fmaf(acc0[j], i0, bv[j]);
            out1[j] = fmaf(acc1[j], i1, bv[j]);
        }
    } else {
        #pragma unroll
        for (int j = 0; j < VW; j++) { out0[j] = bv[j]; out1[j] = bv[j]; }
    }
    if (RELU) {
        #pragma unroll
        for (int j = 0; j < VW; j++) {
            out0[j] = fmaxf(out0[j], 0.f);
            out1[j] = fmaxf(out1[j], 0.f);
        }
    }

    if constexpr (sizeof(OT) == 2) {
        if constexpr (VW == 4) {
            union { __half2 h[2]; uint2 u; } cv0, cv1;
            cv0.h[0] = __floats2half2_rn(out0[0], out0[1]);
            cv0.h[1] = __floats2half2_rn(out0[2], out0[3]);
            cv1.h[0] = __floats2half2_rn(out1[0], out1[1]);
            cv1.h[1] = __floats2half2_rn(out1[2], out1[3]);
            *reinterpret_cast<uint2*>(o0 + (size_t)gw * HD + c0) = cv0.u;
            *reinterpret_cast<uint2*>(o1 + (size_t)gw * HD + c0) = cv1.u;
        } else {
            __half2 v0 = __floats2half2_rn(out0[0], out0[1]);
            __half2 v1 = __floats2half2_rn(out1[0], out1[1]);
            *reinterpret_cast<unsigned*>(o0 + (size_t)gw * HD + c0) =
                *reinterpret_cast<unsigned*>(&v0);
            *reinterpret_cast<unsigned*>(o1 + (size_t)gw * HD + c0) =
                *reinterpret_cast<unsigned*>(&v1);
        }
    } else {
        if constexpr (VW == 4) {
            *reinterpret_cast<float4*>(o0 + (size_t)gw * HD + c0) =
                make_float4(out0[0], out0[1], out0[2], out0[3]);
            *reinterpret_cast<float4*>(o1 + (size_t)gw * HD + c0) =
                make_float4(out1[0], out1[1], out1[2], out1[3]);
        } else {
            *reinterpret_cast<float2*>(o0 + (size_t)gw * HD + c0) =
                make_float2(out0[0], out0[1]);
            *reinterpret_cast<float2*>(o1 + (size_t)gw * HD + c0) =
                make_float2(out1[0], out1[1]);
        }
    }
}

// ---------------- launcher ----------------
extern "C" void kernel_launch(void* const* d_in, const int* in_sizes, int n_in,
                              void* d_out, int out_size)
{
    const float* input = (const float*)d_in[0];
    const int*   src   = (const int*)  d_in[1];
    const int*   dst   = (const int*)  d_in[2];
    const float* W1    = (const float*)d_in[3];
    const float* al1   = (const float*)d_in[4];
    const float* ar1   = (const float*)d_in[5];
    const float* b1    = (const float*)d_in[6];
    const float* W2    = (const float*)d_in[7];
    const float* al2   = (const float*)d_in[8];
    const float* ar2   = (const float*)d_in[9];
    const float* b2    = (const float*)d_in[10];
    const float* W3    = (const float*)d_in[11];
    const float* al3   = (const float*)d_in[12];
    const float* ar3   = (const float*)d_in[13];
    const float* b3    = (const float*)d_in[14];
    float* out = (float*)d_out;

    void *ph, *px, *pw, *pel, *per;
    cudaGetSymbolAddress(&ph,  g_h);
    cudaGetSymbolAddress(&px,  g_x16);
    cudaGetSymbolAddress(&pw,  g_wh);
    cudaGetSymbolAddress(&pel, g_el);
    cudaGetSymbolAddress(&per, g_er);
    __half* hbuf = (__half*)ph;
    __half* x16  = (__half*)px;
    __half* wh   = (__half*)pw;
    float*  elb  = (float*)pel;
    float*  erb  = (float*)per;

    // conversions + CSR build
    conv_x_kernel<<<(BB * NN * DIN / 4 + 255) / 256, 256>>>(input);
    conv_w_kernel<<<(32768 + 255) / 256, 256>>>(W1, W2, W3);
    zero_deg_kernel<<<(NN + 255) / 256, 256>>>();
    hist_kernel<<<(EE + 255) / 256, 256>>>(dst);
    scan_kernel<<<1, 1024>>>();
    scatter_kernel<<<(EE + 255) / 256, 256>>>(src, dst);

    dim3 ggrid((NN + 63) / 64, BB);
    const int agrid = (NN * 32 + 255) / 256;

    // Layer 1: GATConv(64 -> 2 heads x 64)
    mma_gemm_att<64, 128, 2><<<ggrid, 128>>>(x16, wh, al1, ar1, hbuf, elb, erb);
    aggregate_kernel<128, 2, false, __half><<<agrid, 256>>>(hbuf, elb, erb, b1, x16, (size_t)NN * 128);

    // Layer 2: GATConv(128 -> 128, 1 head), ReLU
    mma_gemm_att<128, 128, 1><<<ggrid, 128>>>(x16, wh + 8192, al2, ar2, hbuf, elb, erb);
    aggregate_kernel<128, 1, true, __half><<<agrid, 256>>>(hbuf, elb, erb, b2, x16, (size_t)NN * 128);

    // Layer 3: GATConv(128 -> 64, 1 head)
    mma_gemm_att<128, 64, 1><<<ggrid, 128>>>(x16, wh + 24576, al3, ar3, hbuf, elb, erb);
    aggregate_kernel<64, 1, false, float><<<agrid, 256>>>(hbuf, elb, erb, b3, out, (size_t)NN * DOUTC);
}

// round 12
// speedup vs baseline: 2.2257x; 1.0994x over previous
#include <cuda_runtime.h>
#include <cuda_fp16.h>
#include <math.h>

// Problem constants
#define NN    50000
#define EE    800000
#define DIN   64
#define HIDD  128
#define DOUTC 64
#define BB    2

// ---------------- scratch (static device globals; no allocation) ----------------
// g_h layout is BATCH-INTERLEAVED per node: 32 chunks of 2*VW halves:
// [b0 feats VW*j..][b1 feats VW*j..]
__device__ __half g_h  [BB * NN * 128];  // projected features (interleaved gather table)
__device__ __half g_x16[BB * NN * 128];  // fp16 GEMM input (converted input / fp16 y)
__device__ __half g_wh [32768];          // W1(8192) | W2(16384) | W3(8192) fp16
__device__ float  g_el [BB * NN * 2];    // per-node attention left  (max 2 heads)
__device__ float  g_er [BB * NN * 2];    // per-node attention right
__device__ int    g_rowptr[NN + 1];      // CSR by dst
__device__ int    g_cursor[NN];          // degree / scatter cursor
__device__ int    g_csrc[EE];            // src per CSR slot

__device__ __forceinline__ unsigned smem_u32(const void* p) {
    return (unsigned)__cvta_generic_to_shared(p);
}

__device__ __forceinline__ float2 h2f(unsigned u) {
    return __half22float2(*reinterpret_cast<const __half2*>(&u));
}

// ---------------- fused prep: convert x + W to fp16, zero degree counters ----
__global__ void prep_kernel(const float* __restrict__ in,
                            const float* __restrict__ W1,
                            const float* __restrict__ W2,
                            const float* __restrict__ W3) {
    int i = blockIdx.x * blockDim.x + threadIdx.x;
    if (i < BB * NN * DIN / 4) {
        float4 v = reinterpret_cast<const float4*>(in)[i];
        union { __half2 h[2]; uint2 u; } cv;
        cv.h[0] = __floats2half2_rn(v.x, v.y);
        cv.h[1] = __floats2half2_rn(v.z, v.w);
        reinterpret_cast<uint2*>(g_x16)[i] = cv.u;
    }
    if (i < 32768) {
        if (i < 8192)       g_wh[i] = __float2half_rn(W1[i]);
        else if (i < 24576) g_wh[i] = __float2half_rn(W2[i - 8192]);
        else                g_wh[i] = __float2half_rn(W3[i - 24576]);
    }
    if (i < NN) g_cursor[i] = 0;
}

// ---------------- CSR build ----------------
__global__ void hist_kernel(const int* __restrict__ dst) {
    int e = blockIdx.x * blockDim.x + threadIdx.x;
    if (e < EE) atomicAdd(&g_cursor[dst[e]], 1);
}

__global__ void scan_kernel() {
    __shared__ int ss[1024];
    const int t  = threadIdx.x;
    const int CH = (NN + 1023) / 1024;
    const int b  = t * CH;
    const int e  = min(b + CH, NN);
    int s = 0;
    for (int i = b; i < e; i++) s += g_cursor[i];
    ss[t] = s;
    __syncthreads();
    for (int off = 1; off < 1024; off <<= 1) {
        int v = (t >= off) ? ss[t - off] : 0;
        __syncthreads();
        ss[t] += v;
        __syncthreads();
    }
    int run = (t == 0) ? 0 : ss[t - 1];
    for (int i = b; i < e; i++) {
        int d = g_cursor[i];
        g_rowptr[i] = run;
        g_cursor[i] = run;
        run += d;
    }
    if (t == 1023) g_rowptr[NN] = ss[1023];
}

__global__ void scatter_kernel(const int* __restrict__ src, const int* __restrict__ dst) {
    int e = blockIdx.x * blockDim.x + threadIdx.x;
    if (e < EE) {
        int p = atomicAdd(&g_cursor[dst[e]], 1);
        g_csrc[p] = src[e];
    }
}

// ---------------- HMMA (mma.sync m16n8k16) GEMM + attention epilogue ----------
template <int K, int HD, int H>
__global__ __launch_bounds__(128) void mma_gemm_att(
    const __half* __restrict__ xbase,
    const __half* __restrict__ Wh,
    const float* __restrict__ al, const float* __restrict__ ar,
    __half* __restrict__ hbase, float* __restrict__ elbase, float* __restrict__ erbase)
{
    constexpr int KS = 64;
    constexpr int PX = KS + 8;
    constexpr int PW = HD + 8;
    constexpr int NT = HD / 8;
    constexpr int D  = HD / H;
    constexpr int VW = HD / 32;

    __shared__ __align__(16) __half xs[64 * PX];
    __shared__ __align__(16) __half ws[KS * PW];
    __shared__ float sal[HD], sar[HD];

    const int bb = blockIdx.y;
    const __half* x  = xbase + (size_t)bb * NN * K;
    float*        el = elbase + (size_t)bb * NN * H;
    float*        er = erbase + (size_t)bb * NN * H;

    const int tid  = threadIdx.x;
    const int warp = tid >> 5;
    const int lane = tid & 31;
    const int g    = lane >> 2;
    const int t    = lane & 3;
    const int row0 = blockIdx.x * 64;

    for (int i = tid; i < HD; i += 128) { sal[i] = al[i]; sar[i] = ar[i]; }

    float C[NT][4];
    #pragma unroll
    for (int j = 0; j < NT; j++)
        #pragma unroll
        for (int c = 0; c < 4; c++) C[j][c] = 0.f;

    for (int ko = 0; ko < K; ko += KS) {
        for (int idx = tid; idx < 64 * (KS / 8); idx += 128) {
            int r = idx / (KS / 8), j = idx % (KS / 8);
            int grow = min(row0 + r, NN - 1);
            *reinterpret_cast<uint4*>(&xs[r * PX + j * 8]) =
                *reinterpret_cast<const uint4*>(&x[(size_t)grow * K + ko + j * 8]);
        }
        for (int idx = tid; idx < KS * (HD / 8); idx += 128) {
            int r = idx / (HD / 8), j = idx % (HD / 8);
            *reinterpret_cast<uint4*>(&ws[r * PW + j * 8]) =
                *reinterpret_cast<const uint4*>(&Wh[(size_t)(ko + r) * HD + j * 8]);
        }
        __syncthreads();

        #pragma unroll
        for (int kk = 0; kk < KS; kk += 16) {
            unsigned a0, a1, a2, a3;
            {
                int i8  = lane & 7;
                int sel = lane >> 3;
                int arow = warp * 16 + i8 + (sel & 1) * 8;
                int akk  = kk + (sel >> 1) * 8;
                unsigned addr = smem_u32(&xs[arow * PX + akk]);
                asm volatile("ldmatrix.sync.aligned.m8n8.x4.shared.b16 {%0,%1,%2,%3}, [%4];"
                             : "=r"(a0), "=r"(a1), "=r"(a2), "=r"(a3) : "r"(addr));
            }
            #pragma unroll
            for (int j = 0; j < NT; j++) {
                unsigned b0, b1;
                int i8 = lane & 7;
                int s  = (lane >> 3) & 1;
                unsigned baddr = smem_u32(&ws[(kk + s * 8 + i8) * PW + j * 8]);
                asm volatile("ldmatrix.sync.aligned.m8n8.x2.trans.shared.b16 {%0,%1}, [%2];"
                             : "=r"(b0), "=r"(b1) : "r"(baddr));
                asm volatile("mma.sync.aligned.m16n8k16.row.col.f32.f16.f16.f32 "
                             "{%0,%1,%2,%3}, {%4,%5,%6,%7}, {%8,%9}, {%0,%1,%2,%3};"
                             : "+f"(C[j][0]), "+f"(C[j][1]), "+f"(C[j][2]), "+f"(C[j][3])
                             : "r"(a0), "r"(a1), "r"(a2), "r"(a3), "r"(b0), "r"(b1));
            }
        }
        __syncthreads();
    }

    const int row_a = row0 + warp * 16 + g;
    const int row_b = row_a + 8;

    float pelA[H], perA[H], pelB[H], perB[H];
    #pragma unroll
    for (int h = 0; h < H; h++) { pelA[h] = 0.f; perA[h] = 0.f; pelB[h] = 0.f; perB[h] = 0.f; }

    #pragma unroll
    for (int j = 0; j < NT; j++) {
        const int cc = j * 8 + 2 * t;
        const int hh = (j * 8) / D;
        const float a0v = sal[cc], a1v = sal[cc + 1];
        const float r0v = sar[cc], r1v = sar[cc + 1];
        pelA[hh] = fmaf(C[j][0], a0v, fmaf(C[j][1], a1v, pelA[hh]));
        perA[hh] = fmaf(C[j][0], r0v, fmaf(C[j][1], r1v, perA[hh]));
        pelB[hh] = fmaf(C[j][2], a0v, fmaf(C[j][3], a1v, pelB[hh]));
        perB[hh] = fmaf(C[j][2], r0v, fmaf(C[j][3], r1v, perB[hh]));
        const int ioff = (cc / VW) * (2 * VW) + bb * VW + (cc % VW);
        if (row_a < NN) {
            __half2 hv = __floats2half2_rn(C[j][0], C[j][1]);
            *reinterpret_cast<unsigned*>(&hbase[(size_t)row_a * (2 * HD) + ioff]) =
                *reinterpret_cast<unsigned*>(&hv);
        }
        if (row_b < NN) {
            __half2 hv = __floats2half2_rn(C[j][2], C[j][3]);
            *reinterpret_cast<unsigned*>(&hbase[(size_t)row_b * (2 * HD) + ioff]) =
                *reinterpret_cast<unsigned*>(&hv);
        }
    }

    #pragma unroll
    for (int h = 0; h < H; h++) {
        pelA[h] += __shfl_xor_sync(0xffffffffu, pelA[h], 1);
        pelA[h] += __shfl_xor_sync(0xffffffffu, pelA[h], 2);
        perA[h] += __shfl_xor_sync(0xffffffffu, perA[h], 1);
        perA[h] += __shfl_xor_sync(0xffffffffu, perA[h], 2);
        pelB[h] += __shfl_xor_sync(0xffffffffu, pelB[h], 1);
        pelB[h] += __shfl_xor_sync(0xffffffffu, pelB[h], 2);
        perB[h] += __shfl_xor_sync(0xffffffffu, perB[h], 1);
        perB[h] += __shfl_xor_sync(0xffffffffu, perB[h], 2);
    }
    if (t == 0) {
        #pragma unroll
        for (int h = 0; h < H; h++) {
            if (row_a < NN) { el[row_a * H + h] = pelA[h]; er[row_a * H + h] = perA[h]; }
            if (row_b < NN) { el[row_b * H + h] = pelB[h]; er[row_b * H + h] = perB[h]; }
        }
    }
}

// ---------------- warp-cooperative edge-softmax + aggregation ----------------
// Per 32-edge chunk: ONE coalesced csrc load; each lane computes its edge's
// weights (exp once per edge, all heads/batches) and stages (idx, w) in smem;
// inner loop streams independent h-gathers fed by LDS broadcasts.
template <int HD, int H, bool RELU, typename OT>
__global__ __launch_bounds__(256) void aggregate_kernel(
    const __half* __restrict__ hbase, const float* __restrict__ elbase,
    const float* __restrict__ erbase, const float* __restrict__ bias,
    OT* __restrict__ outbase, size_t outstride)
{
    constexpr int VW = HD / 32;
    constexpr int D  = HD / H;

    __shared__ int   sidx[8][32];
    __shared__ float swgt[8][32 * 2 * H];

    const float*  el0 = elbase;
    const float*  el1 = elbase + (size_t)NN * H;
    const float*  er0 = erbase;
    const float*  er1 = erbase + (size_t)NN * H;
    OT*           o0  = outbase;
    OT*           o1  = outbase + outstride;

    const int warp = threadIdx.x >> 5;
    const int lane = threadIdx.x & 31;
    const int gw   = (blockIdx.x * blockDim.x + threadIdx.x) >> 5;
    if (gw >= NN) return;

    const int s0 = g_rowptr[gw];
    const int s1 = g_rowptr[gw + 1];
    const int c0 = lane * VW;
    const int hl = c0 / D;
    const int loff = lane * (2 * VW);

    float erA[H], erB[H];
    #pragma unroll
    for (int h = 0; h < H; h++) {
        erA[h] = er0[gw * H + h];
        erB[h] = er1[gw * H + h];
    }

    float acc0[VW], acc1[VW];
    #pragma unroll
    for (int j = 0; j < VW; j++) { acc0[j] = 0.f; acc1[j] = 0.f; }
    float psum0[H], psum1[H];
    #pragma unroll
    for (int h = 0; h < H; h++) { psum0[h] = 0.f; psum1[h] = 0.f; }

    for (int p = s0; p < s1; p += 32) {
        const int n = min(32, s1 - p);
        // ---- prep: lane handles edge p+lane ----
        if (lane < n) {
            const int idx = g_csrc[p + lane];
            sidx[warp][lane] = idx;
            #pragma unroll
            for (int h = 0; h < H; h++) {
                float v0 = el0[idx * H + h] + erA[h];
                float v1 = el1[idx * H + h] + erB[h];
                v0 = (v0 > 0.f) ? v0 : 0.2f * v0;
                v1 = (v1 > 0.f) ? v1 : 0.2f * v1;
                const float w0 = __expf(v0);
                const float w1 = __expf(v1);
                swgt[warp][lane * 2 * H + h]     = w0;
                swgt[warp][lane * 2 * H + H + h] = w1;
                psum0[h] += w0;
                psum1[h] += w1;
            }
        }
        __syncwarp();
        // ---- stream gathers ----
        #pragma unroll 4
        for (int j = 0; j < n; j++) {
            const int sj = sidx[warp][j];
            const float wj0 = swgt[warp][j * 2 * H + hl];
            const float wj1 = swgt[warp][j * 2 * H + H + hl];
            const __half* pA = hbase + (size_t)sj * (2 * HD) + loff;
            if constexpr (VW == 4) {
                uint4 u = *reinterpret_cast<const uint4*>(pA);
                float2 a = h2f(u.x), b = h2f(u.y);   // batch0
                float2 c = h2f(u.z), d = h2f(u.w);   // batch1
                acc0[0] = fmaf(wj0, a.x, acc0[0]);
                acc0[1] = fmaf(wj0, a.y, acc0[1]);
                acc0[2] = fmaf(wj0, b.x, acc0[2]);
                acc0[3] = fmaf(wj0, b.y, acc0[3]);
                acc1[0] = fmaf(wj1, c.x, acc1[0]);
                acc1[1] = fmaf(wj1, c.y, acc1[1]);
                acc1[2] = fmaf(wj1, d.x, acc1[2]);
                acc1[3] = fmaf(wj1, d.y, acc1[3]);
            } else {
                uint2 u = *reinterpret_cast<const uint2*>(pA);
                float2 a = h2f(u.x);                  // batch0
                float2 c = h2f(u.y);                  // batch1
                acc0[0] = fmaf(wj0, a.x, acc0[0]);
                acc0[1] = fmaf(wj0, a.y, acc0[1]);
                acc1[0] = fmaf(wj1, c.x, acc1[0]);
                acc1[1] = fmaf(wj1, c.y, acc1[1]);
            }
        }
        __syncwarp();
    }

    // ---- reduce per-lane partial sums across the warp ----
    #pragma unroll
    for (int h = 0; h < H; h++) {
        #pragma unroll
        for (int off = 16; off > 0; off >>= 1) {
            psum0[h] += __shfl_xor_sync(0xffffffffu, psum0[h], off);
            psum1[h] += __shfl_xor_sync(0xffffffffu, psum1[h], off);
        }
    }
    const float sum0 = psum0[hl];
    const float sum1 = psum1[hl];

    float bv[VW];
    #pragma unroll
    for (int j = 0; j < VW; j++) bv[j] = bias[c0 + j];

    float out0[VW], out1[VW];
    if (s1 > s0) {
        const float i0 = 1.f / sum0;
        const float i1 = 1.f / sum1;
        #pragma unroll
        for (int j = 0; j < VW; j++) {
            out0[j] = fmaf(acc0[j], i0, bv[j]);
            out1[j] = fmaf(acc1[j], i1, bv[j]);
        }
    } else {
        #pragma unroll
        for (int j = 0; j < VW; j++) { out0[j] = bv[j]; out1[j] = bv[j]; }
    }
    if (RELU) {
        #pragma unroll
        for (int j = 0; j < VW; j++) {
            out0[j] = fmaxf(out0[j], 0.f);
            out1[j] = fmaxf(out1[j], 0.f);
        }
    }

    if constexpr (sizeof(OT) == 2) {
        if constexpr (VW == 4) {
            union { __half2 h[2]; uint2 u; } cv0, cv1;
            cv0.h[0] = __floats2half2_rn(out0[0], out0[1]);
            cv0.h[1] = __floats2half2_rn(out0[2], out0[3]);
            cv1.h[0] = __floats2half2_rn(out1[0], out1[1]);
            cv1.h[1] = __floats2half2_rn(out1[2], out1[3]);
            *reinterpret_cast<uint2*>(o0 + (size_t)gw * HD + c0) = cv0.u;
            *reinterpret_cast<uint2*>(o1 + (size_t)gw * HD + c0) = cv1.u;
        } else {
            __half2 v0 = __floats2half2_rn(out0[0], out0[1]);
            __half2 v1 = __floats2half2_rn(out1[0], out1[1]);
            *reinterpret_cast<unsigned*>(o0 + (size_t)gw * HD + c0) =
                *reinterpret_cast<unsigned*>(&v0);
            *reinterpret_cast<unsigned*>(o1 + (size_t)gw * HD + c0) =
                *reinterpret_cast<unsigned*>(&v1);
        }
    } else {
        if constexpr (VW == 4) {
            *reinterpret_cast<float4*>(o0 + (size_t)gw * HD + c0) =
                make_float4(out0[0], out0[1], out0[2], out0[3]);
            *reinterpret_cast<float4*>(o1 + (size_t)gw * HD + c0) =
                make_float4(out1[0], out1[1], out1[2], out1[3]);
        } else {
            *reinterpret_cast<float2*>(o0 + (size_t)gw * HD + c0) =
                make_float2(out0[0], out0[1]);
            *reinterpret_cast<float2*>(o1 + (size_t)gw * HD + c0) =
                make_float2(out1[0], out1[1]);
        }
    }
}

// ---------------- launcher ----------------
extern "C" void kernel_launch(void* const* d_in, const int* in_sizes, int n_in,
                              void* d_out, int out_size)
{
    const float* input = (const float*)d_in[0];
    const int*   src   = (const int*)  d_in[1];
    const int*   dst   = (const int*)  d_in[2];
    const float* W1    = (const float*)d_in[3];
    const float* al1   = (const float*)d_in[4];
    const float* ar1   = (const float*)d_in[5];
    const float* b1    = (const float*)d_in[6];
    const float* W2    = (const float*)d_in[7];
    const float* al2   = (const float*)d_in[8];
    const float* ar2   = (const float*)d_in[9];
    const float* b2    = (const float*)d_in[10];
    const float* W3    = (const float*)d_in[11];
    const float* al3   = (const float*)d_in[12];
    const float* ar3   = (const float*)d_in[13];
    const float* b3    = (const float*)d_in[14];
    float* out = (float*)d_out;

    void *ph, *px, *pw, *pel, *per;
    cudaGetSymbolAddress(&ph,  g_h);
    cudaGetSymbolAddress(&px,  g_x16);
    cudaGetSymbolAddress(&pw,  g_wh);
    cudaGetSymbolAddress(&pel, g_el);
    cudaGetSymbolAddress(&per, g_er);
    __half* hbuf = (__half*)ph;
    __half* x16  = (__half*)px;
    __half* wh   = (__half*)pw;
    float*  elb  = (float*)pel;
    float*  erb  = (float*)per;

    // fused prep (convert + zero) + CSR build
    prep_kernel<<<(BB * NN * DIN / 4 + 255) / 256, 256>>>(input, W1, W2, W3);
    hist_kernel<<<(EE + 255) / 256, 256>>>(dst);
    scan_kernel<<<1, 1024>>>();
    scatter_kernel<<<(EE + 255) / 256, 256>>>(src, dst);

    dim3 ggrid((NN + 63) / 64, BB);
    const int agrid = (NN * 32 + 255) / 256;

    // Layer 1: GATConv(64 -> 2 heads x 64)
    mma_gemm_att<64, 128, 2><<<ggrid, 128>>>(x16, wh, al1, ar1, hbuf, elb, erb);
    aggregate_kernel<128, 2, false, __half><<<agrid, 256>>>(hbuf, elb, erb, b1, x16, (size_t)NN * 128);

    // Layer 2: GATConv(128 -> 128, 1 head), ReLU
    mma_gemm_att<128, 128, 1><<<ggrid, 128>>>(x16, wh + 8192, al2, ar2, hbuf, elb, erb);
    aggregate_kernel<128, 1, true, __half><<<agrid, 256>>>(hbuf, elb, erb, b2, x16, (size_t)NN * 128);

    // Layer 3: GATConv(128 -> 64, 1 head)
    mma_gemm_att<128, 64, 1><<<ggrid, 128>>>(x16, wh + 24576, al3, ar3, hbuf, elb, erb);
    aggregate_kernel<64, 1, false, float><<<agrid, 256>>>(hbuf, elb, erb, b3, out, (size_t)NN * DOUTC);
}